// round 3
// baseline (speedup 1.0000x reference)
#include <cuda_runtime.h>
#include <cuda_bf16.h>
#include <math.h>

// Problem dims
#define Bb   4
#define Nn   2048
#define DIMd 768
#define Hh   12
#define DHd  64
#define MLPm 3072
#define Ll   2
#define Mrows (Bb*Nn)   // 8192

// ---------------- scratch (device globals: allocation-free) ----------------
__device__ float g_x [Mrows*DIMd];
__device__ float g_xn[Mrows*DIMd];
__device__ float g_q [Mrows*DIMd];
__device__ float g_kv[Mrows*2*DIMd];
__device__ float g_ao[Mrows*DIMd];
__device__ float g_h [Mrows*MLPm];

// ---------------- LayerNorm: one block per row of 768 ----------------
__global__ void __launch_bounds__(256) ln_k(const float* __restrict__ X,
                                            const float* __restrict__ g,
                                            float* __restrict__ Y)
{
    int row = blockIdx.x;
    const float* x = X + (size_t)row * DIMd;
    int tid = threadIdx.x;
    float v[3]; float s = 0.f, sq = 0.f;
#pragma unroll
    for (int i = 0; i < 3; i++) {
        v[i] = x[tid + i * 256];
        s += v[i]; sq += v[i] * v[i];
    }
#pragma unroll
    for (int o = 16; o; o >>= 1) {
        s  += __shfl_xor_sync(~0u, s, o);
        sq += __shfl_xor_sync(~0u, sq, o);
    }
    __shared__ float red[2][8];
    int w = tid >> 5, lane = tid & 31;
    if (lane == 0) { red[0][w] = s; red[1][w] = sq; }
    __syncthreads();
    s = 0.f; sq = 0.f;
#pragma unroll
    for (int j = 0; j < 8; j++) { s += red[0][j]; sq += red[1][j]; }
    float mean = s * (1.f / DIMd);
    float var  = sq * (1.f / DIMd) - mean * mean;
    float rstd = rsqrtf(var + 1e-5f);
    float* y = Y + (size_t)row * DIMd;
#pragma unroll
    for (int i = 0; i < 3; i++) {
        int c = tid + i * 256;
        y[c] = (v[i] - mean) * rstd * g[c];
    }
}

// ---------------- generic GEMM: C[M,Nc] = A[M,K] * W[K,Nc] (+epilogue) ------
// EPI: 0 none, 1 +bias, 2 gelu(x+bias), 3 +res, 4 +bias+res
#define BM 128
#define BN 64
#define BK 16
template<int EPI>
__global__ void __launch_bounds__(256) gemm_k(const float* __restrict__ A,
                                              const float* __restrict__ W,
                                              const float* __restrict__ bias,
                                              const float* __restrict__ res,
                                              float* __restrict__ C,
                                              int K, int Nc)
{
    __shared__ float As[BK][BM + 4];
    __shared__ float Ws[BK][BN + 4];
    int tid = threadIdx.x;
    int tx = tid & 15, ty = tid >> 4;
    int m0 = blockIdx.y * BM, n0 = blockIdx.x * BN;
    const float* Ag = A + (size_t)m0 * K;
    const float* Wg = W + n0;
    float acc[8][4] = {};

    for (int k0 = 0; k0 < K; k0 += BK) {
#pragma unroll
        for (int i = 0; i < 2; i++) {
            int idx = tid * 2 + i;          // 0..511
            int r = idx >> 2;               // 0..127
            int kc = (idx & 3) << 2;        // 0,4,8,12
            float4 a = *(const float4*)(Ag + (size_t)r * K + k0 + kc);
            As[kc + 0][r] = a.x; As[kc + 1][r] = a.y;
            As[kc + 2][r] = a.z; As[kc + 3][r] = a.w;
        }
        {
            int r = tid >> 4;               // 0..15
            int c = (tid & 15) << 2;        // 0..60
            float4 wv = *(const float4*)(Wg + (size_t)(k0 + r) * Nc + c);
            *(float4*)&Ws[r][c] = wv;
        }
        __syncthreads();
#pragma unroll
        for (int kk = 0; kk < BK; kk++) {
            float4 a0 = *(const float4*)&As[kk][ty * 8];
            float4 a1 = *(const float4*)&As[kk][ty * 8 + 4];
            float4 b  = *(const float4*)&Ws[kk][tx * 4];
            float av[8] = {a0.x, a0.y, a0.z, a0.w, a1.x, a1.y, a1.z, a1.w};
            float bv[4] = {b.x, b.y, b.z, b.w};
#pragma unroll
            for (int i = 0; i < 8; i++)
#pragma unroll
                for (int j = 0; j < 4; j++)
                    acc[i][j] += av[i] * bv[j];
        }
        __syncthreads();
    }

    float bv[4] = {0.f, 0.f, 0.f, 0.f};
    if (EPI == 1 || EPI == 2 || EPI == 4) {
        float4 bb = *(const float4*)(bias + n0 + tx * 4);
        bv[0] = bb.x; bv[1] = bb.y; bv[2] = bb.z; bv[3] = bb.w;
    }
#pragma unroll
    for (int i = 0; i < 8; i++) {
        size_t row = (size_t)(m0 + ty * 8 + i);
        size_t off = row * Nc + n0 + tx * 4;
        float vv[4];
#pragma unroll
        for (int j = 0; j < 4; j++) {
            float v = acc[i][j];
            if (EPI == 1 || EPI == 2 || EPI == 4) v += bv[j];
            if (EPI == 2) v = 0.5f * v * (1.0f + erff(v * 0.70710678118654752f));
            vv[j] = v;
        }
        if (EPI == 3 || EPI == 4) {
            float4 rr = *(const float4*)(res + off);
            vv[0] += rr.x; vv[1] += rr.y; vv[2] += rr.z; vv[3] += rr.w;
        }
        float4 ov = make_float4(vv[0], vv[1], vv[2], vv[3]);
        *(float4*)(C + off) = ov;
    }
}

// ---------------- QK RMSNorm + 2D RoPE (one warp per (b,n,h) row) ----------
__global__ void __launch_bounds__(256) qkrope_k(float* __restrict__ Q,
                                                float* __restrict__ KV,
                                                const float* __restrict__ qg,
                                                const float* __restrict__ kg,
                                                const int* __restrict__ h_idx,
                                                const int* __restrict__ w_idx)
{
    int warp = blockIdx.x * 8 + (threadIdx.x >> 5);
    int lane = threadIdx.x & 31;
    int which = (warp >= Mrows * Hh) ? 1 : 0;        // 0 = Q, 1 = K
    int rid = which ? warp - Mrows * Hh : warp;
    int bn = rid / Hh;
    int h  = rid % Hh;
    float* ptr;
    const float* g;
    if (!which) { ptr = Q  + (size_t)bn * DIMd   + h * DHd; g = qg + h * DHd; }
    else        { ptr = KV + (size_t)bn * 2*DIMd + h * DHd; g = kg + h * DHd; }

    float v1 = ptr[lane], v2 = ptr[lane + 32];
    float ss = v1 * v1 + v2 * v2;
#pragma unroll
    for (int o = 16; o; o >>= 1) ss += __shfl_xor_sync(~0u, ss, o);
    float sc = 8.0f / fmaxf(sqrtf(ss), 1e-12f);
    v1 = v1 * sc * g[lane];
    v2 = v2 * sc * g[lane + 32];

    int f = lane & 15;
    // inv_freq = 10000^(-f/16)
    float invf = exp2f(-(float)f * (13.287712379549449f / 16.0f));
    float th1 = (float)h_idx[bn] * invf;
    float th2 = (float)w_idx[bn] * invf;
    float p1 = __shfl_xor_sync(~0u, v1, 16);
    float p2 = __shfl_xor_sync(~0u, v2, 16);
    float rh1 = (lane < 16) ? -p1 : p1;
    float rh2 = (lane < 16) ? -p2 : p2;
    ptr[lane]      = v1 * cosf(th1) + rh1 * sinf(th1);
    ptr[lane + 32] = v2 * cosf(th2) + rh2 * sinf(th2);
}

// ---------------- Flash-style attention, 64x64 tiles, length-masked --------
#define SROW 68
__global__ void __launch_bounds__(256) attn_k(const float* __restrict__ Q,
                                              const float* __restrict__ KV,
                                              const int* __restrict__ lengths,
                                              float* __restrict__ O)
{
    extern __shared__ float sm[];
    float (*Qs)[SROW] = (float(*)[SROW])(sm);
    float (*Ks)[SROW] = (float(*)[SROW])(sm + 64 * SROW);
    float (*Vs)[SROW] = (float(*)[SROW])(sm + 2 * 64 * SROW);
    float (*Ps)[SROW] = (float(*)[SROW])(sm + 3 * 64 * SROW);

    int b = blockIdx.z, h = blockIdx.y, n0 = blockIdx.x * 64;
    int tid = threadIdx.x, tx = tid & 15, ty = tid >> 4;

    const float* Qg = Q  + ((size_t)b * Nn + n0) * DIMd + h * DHd;   // stride 768
    const float* Kg = KV + ((size_t)b * Nn) * 2*DIMd + h * DHd;      // stride 1536
    int len = lengths[b];

    // load Q tile transposed: Qs[d][q]
#pragma unroll
    for (int i = 0; i < 4; i++) {
        int idx = tid * 4 + i;          // 1024 float4 = 4096 floats
        int r = idx >> 4;               // 0..63
        int c = (idx & 15) << 2;        // 0..60
        float4 a = *(const float4*)(Qg + (size_t)r * DIMd + c);
        Qs[c + 0][r] = a.x; Qs[c + 1][r] = a.y;
        Qs[c + 2][r] = a.z; Qs[c + 3][r] = a.w;
    }

    float o[4][4] = {};
    float m[4], l[4];
#pragma unroll
    for (int i = 0; i < 4; i++) { m[i] = -1e30f; l[i] = 0.f; }

    int nt = (len + 63) >> 6;
    for (int kt = 0; kt < nt; kt++) {
        __syncthreads();   // protects Ks/Vs/Ps reuse from previous iteration
        // load K,V tiles: Ks[d][key] (transposed), Vs[key][d]
#pragma unroll
        for (int i = 0; i < 4; i++) {
            int idx = tid * 4 + i;
            int r = idx >> 4;
            int c = (idx & 15) << 2;
            const float* kp = Kg + (size_t)(kt * 64 + r) * (2*DIMd) + c;
            float4 a = *(const float4*)kp;
            Ks[c + 0][r] = a.x; Ks[c + 1][r] = a.y;
            Ks[c + 2][r] = a.z; Ks[c + 3][r] = a.w;
            float4 vv = *(const float4*)(kp + DIMd);   // V lives +768 in kv
            *(float4*)&Vs[r][c] = vv;
        }
        __syncthreads();

        // S = Q * K^T
        float s[4][4] = {};
#pragma unroll 8
        for (int kk = 0; kk < 64; kk++) {
            float4 qa = *(const float4*)&Qs[kk][ty * 4];
            float4 ka = *(const float4*)&Ks[kk][tx * 4];
            float av[4] = {qa.x, qa.y, qa.z, qa.w};
            float bvv[4] = {ka.x, ka.y, ka.z, ka.w};
#pragma unroll
            for (int i = 0; i < 4; i++)
#pragma unroll
                for (int j = 0; j < 4; j++)
                    s[i][j] += av[i] * bvv[j];
        }

        // key mask
        int kbase = kt * 64 + tx * 4;
#pragma unroll
        for (int j = 0; j < 4; j++)
            if (kbase + j >= len)
#pragma unroll
                for (int i = 0; i < 4; i++) s[i][j] = -1e30f;

        // online softmax
#pragma unroll
        for (int i = 0; i < 4; i++) {
            float rm = fmaxf(fmaxf(s[i][0], s[i][1]), fmaxf(s[i][2], s[i][3]));
#pragma unroll
            for (int oo = 1; oo < 16; oo <<= 1)
                rm = fmaxf(rm, __shfl_xor_sync(~0u, rm, oo));
            float mn = fmaxf(m[i], rm);
            float rs = 0.f;
#pragma unroll
            for (int j = 0; j < 4; j++) {
                s[i][j] = __expf(s[i][j] - mn);
                rs += s[i][j];
            }
#pragma unroll
            for (int oo = 1; oo < 16; oo <<= 1)
                rs += __shfl_xor_sync(~0u, rs, oo);
            float corr = __expf(m[i] - mn);
            l[i] = l[i] * corr + rs;
            m[i] = mn;
#pragma unroll
            for (int j = 0; j < 4; j++) o[i][j] *= corr;
        }

        // stage P transposed: Ps[key][query]
#pragma unroll
        for (int i = 0; i < 4; i++)
#pragma unroll
            for (int j = 0; j < 4; j++)
                Ps[tx * 4 + j][ty * 4 + i] = s[i][j];
        __syncthreads();

        // O += P * V
#pragma unroll 8
        for (int kk = 0; kk < 64; kk++) {
            float4 pa = *(const float4*)&Ps[kk][ty * 4];
            float4 va = *(const float4*)&Vs[kk][tx * 4];
            float av[4] = {pa.x, pa.y, pa.z, pa.w};
            float bvv[4] = {va.x, va.y, va.z, va.w};
#pragma unroll
            for (int i = 0; i < 4; i++)
#pragma unroll
                for (int j = 0; j < 4; j++)
                    o[i][j] += av[i] * bvv[j];
        }
    }

    // write out  (layout [B,N,H*DH])
#pragma unroll
    for (int i = 0; i < 4; i++) {
        float inv = 1.0f / l[i];
        int row = n0 + ty * 4 + i;
        float4 r = make_float4(o[i][0] * inv, o[i][1] * inv,
                               o[i][2] * inv, o[i][3] * inv);
        *(float4*)&O[((size_t)b * Nn + row) * DIMd + h * DHd + tx * 4] = r;
    }
}

// ---------------- mask tail writer -----------------------------------------
__global__ void mask_k(const int* __restrict__ lengths, float* __restrict__ out)
{
    int i = blockIdx.x * blockDim.x + threadIdx.x;
    if (i < Bb * Nn) {
        int b = i / Nn, n = i % Nn;
        out[i] = (n < lengths[b]) ? 1.0f : 0.0f;
    }
}

// ---------------- host orchestration ---------------------------------------
extern "C" void kernel_launch(void* const* d_in, const int* in_sizes, int n_in,
                              void* d_out, int out_size)
{
    const float* patches    = (const float*)d_in[0];
    const float* pe_ln1_g   = (const float*)d_in[1];
    const float* pe_W       = (const float*)d_in[2];
    const float* pe_b       = (const float*)d_in[3];
    const float* pe_ln2_g   = (const float*)d_in[4];
    const float* attn_ln_g  = (const float*)d_in[5];
    const float* qn_g       = (const float*)d_in[6];
    const float* kn_g       = (const float*)d_in[7];
    const float* Wq         = (const float*)d_in[8];
    const float* Wkv        = (const float*)d_in[9];
    const float* Wo         = (const float*)d_in[10];
    const float* ff_ln_g    = (const float*)d_in[11];
    const float* W1         = (const float*)d_in[12];
    const float* b1         = (const float*)d_in[13];
    const float* W2         = (const float*)d_in[14];
    const float* b2         = (const float*)d_in[15];
    const float* final_ln_g = (const float*)d_in[16];
    const int*   h_idx      = (const int*)d_in[17];
    const int*   w_idx      = (const int*)d_in[18];
    const int*   lengths    = (const int*)d_in[19];

    float *x, *xn, *q, *kv, *ao, *hb;
    cudaGetSymbolAddress((void**)&x,  g_x);
    cudaGetSymbolAddress((void**)&xn, g_xn);
    cudaGetSymbolAddress((void**)&q,  g_q);
    cudaGetSymbolAddress((void**)&kv, g_kv);
    cudaGetSymbolAddress((void**)&ao, g_ao);
    cudaGetSymbolAddress((void**)&hb, g_h);

    const int ATTN_SMEM = 4 * 64 * SROW * (int)sizeof(float);   // 69632
    cudaFuncSetAttribute(attn_k, cudaFuncAttributeMaxDynamicSharedMemorySize,
                         ATTN_SMEM);

    dim3 t256(256);
    dim3 gN768(DIMd / BN, Mrows / BM);     // (12, 64)
    dim3 gN1536(2 * DIMd / BN, Mrows / BM);
    dim3 gN3072(MLPm / BN, Mrows / BM);

    // patch embedding: LN -> Linear+bias -> LN
    ln_k<<<Mrows, t256>>>(patches, pe_ln1_g, xn);
    gemm_k<1><<<gN768, t256>>>(xn, pe_W, pe_b, nullptr, x, DIMd, DIMd);
    ln_k<<<Mrows, t256>>>(x, pe_ln2_g, x);

    for (int i = 0; i < Ll; i++) {
        ln_k<<<Mrows, t256>>>(x, attn_ln_g + (size_t)i * DIMd, xn);
        gemm_k<0><<<gN768, t256>>>(xn, Wq + (size_t)i * DIMd * DIMd,
                                   nullptr, nullptr, q, DIMd, DIMd);
        gemm_k<0><<<gN1536, t256>>>(xn, Wkv + (size_t)i * DIMd * 2 * DIMd,
                                    nullptr, nullptr, kv, DIMd, 2 * DIMd);
        qkrope_k<<<(2 * Mrows * Hh) / 8, t256>>>(
            q, kv, qn_g + (size_t)i * Hh * DHd, kn_g + (size_t)i * Hh * DHd,
            h_idx, w_idx);
        attn_k<<<dim3(Nn / 64, Hh, Bb), t256, ATTN_SMEM>>>(q, kv, lengths, ao);
        gemm_k<3><<<gN768, t256>>>(ao, Wo + (size_t)i * DIMd * DIMd,
                                   nullptr, x, x, DIMd, DIMd);
        ln_k<<<Mrows, t256>>>(x, ff_ln_g + (size_t)i * DIMd, xn);
        gemm_k<2><<<gN3072, t256>>>(xn, W1 + (size_t)i * DIMd * MLPm,
                                    b1 + (size_t)i * MLPm, nullptr, hb,
                                    DIMd, MLPm);
        gemm_k<4><<<gN768, t256>>>(hb, W2 + (size_t)i * MLPm * DIMd,
                                   b2 + (size_t)i * DIMd, x, x, MLPm, DIMd);
    }

    ln_k<<<Mrows, t256>>>(x, final_ln_g, (float*)d_out);

    // mask tail (if the flattened output carries it)
    if (out_size > Mrows * DIMd) {
        mask_k<<<(Bb * Nn + 255) / 256, t256>>>(lengths,
                                                (float*)d_out + (size_t)Mrows * DIMd);
    }
}

// round 4
// speedup vs baseline: 2.8493x; 2.8493x over previous
#include <cuda_runtime.h>
#include <cuda_bf16.h>
#include <math.h>

// Problem dims
#define Bb   4
#define Nn   2048
#define DIMd 768
#define Hh   12
#define DHd  64
#define MLPm 3072
#define Ll   2
#define Mrows (Bb*Nn)   // 8192

// ---------------- scratch (device globals: allocation-free) ----------------
__device__ float g_x [Mrows*DIMd];
__device__ float g_xn[Mrows*DIMd];
__device__ float g_q [Mrows*DIMd];
__device__ float g_kv[Mrows*2*DIMd];
__device__ float g_ao[Mrows*DIMd];
__device__ float g_h [Mrows*MLPm];

// ---------------- PTX helpers ----------------------------------------------
__device__ __forceinline__ unsigned cvta_s(const void* p) {
    return (unsigned)__cvta_generic_to_shared(p);
}
#define CPA16(dst, src) asm volatile("cp.async.cg.shared.global [%0], [%1], 16;" :: "r"(dst), "l"(src))
#define CPCOMMIT()      asm volatile("cp.async.commit_group;")
#define CPWAIT1()       asm volatile("cp.async.wait_group 1;")
#define CPWAIT0()       asm volatile("cp.async.wait_group 0;")

__device__ __forceinline__ float tf32r(float x) {
    float r;
    asm("cvt.rna.tf32.f32 %0, %1;" : "=f"(r) : "f"(x));
    return r;
}

__device__ __forceinline__ void mma8(float& c0, float& c1, float& c2, float& c3,
                                     float a0, float a1, float a2, float a3,
                                     float b0, float b1) {
    asm volatile(
        "mma.sync.aligned.m16n8k8.row.col.f32.tf32.tf32.f32 "
        "{%0,%1,%2,%3},{%4,%5,%6,%7},{%8,%9},{%0,%1,%2,%3};"
        : "+f"(c0), "+f"(c1), "+f"(c2), "+f"(c3)
        : "r"(__float_as_uint(a0)), "r"(__float_as_uint(a1)),
          "r"(__float_as_uint(a2)), "r"(__float_as_uint(a3)),
          "r"(__float_as_uint(b0)), "r"(__float_as_uint(b1)));
}

// ---------------- LayerNorm: one block per row of 768 ----------------
__global__ void __launch_bounds__(256) ln_k(const float* __restrict__ X,
                                            const float* __restrict__ g,
                                            float* __restrict__ Y)
{
    int row = blockIdx.x;
    const float* x = X + (size_t)row * DIMd;
    int tid = threadIdx.x;
    float v[3]; float s = 0.f, sq = 0.f;
#pragma unroll
    for (int i = 0; i < 3; i++) {
        v[i] = x[tid + i * 256];
        s += v[i]; sq += v[i] * v[i];
    }
#pragma unroll
    for (int o = 16; o; o >>= 1) {
        s  += __shfl_xor_sync(~0u, s, o);
        sq += __shfl_xor_sync(~0u, sq, o);
    }
    __shared__ float red[2][8];
    int w = tid >> 5, lane = tid & 31;
    if (lane == 0) { red[0][w] = s; red[1][w] = sq; }
    __syncthreads();
    s = 0.f; sq = 0.f;
#pragma unroll
    for (int j = 0; j < 8; j++) { s += red[0][j]; sq += red[1][j]; }
    float mean = s * (1.f / DIMd);
    float var  = sq * (1.f / DIMd) - mean * mean;
    float rstd = rsqrtf(var + 1e-5f);
    float* y = Y + (size_t)row * DIMd;
#pragma unroll
    for (int i = 0; i < 3; i++) {
        int c = tid + i * 256;
        y[c] = (v[i] - mean) * rstd * g[c];
    }
}

// ---------------- TF32 tensor-core GEMM: C[M,Nc] = A[M,K]*W[K,Nc] ----------
// CTA tile 128x256, K-step 32, 8 warps each 64x64, double-buffered cp.async.
// EPI: 0 none, 1 +bias, 2 gelu(x+bias), 3 +res, 4 +bias+res
#define AS_LD 36     // A smem row stride (floats): banks (4g+t) distinct
#define WS_LD 264    // W smem row stride (floats): banks (8t+g) distinct
#define AS_SZ (128*AS_LD)
#define WS_SZ (32*WS_LD)

template<int EPI>
__global__ void __launch_bounds__(256) gemm_tc(const float* __restrict__ A,
                                               const float* __restrict__ W,
                                               const float* __restrict__ bias,
                                               const float* __restrict__ res,
                                               float* __restrict__ C,
                                               int K, int Nc)
{
    extern __shared__ float sm[];
    float* Asb = sm;                 // 2 * AS_SZ
    float* Wsb = sm + 2 * AS_SZ;     // 2 * WS_SZ

    int tid = threadIdx.x;
    int warp = tid >> 5, lane = tid & 31;
    int g = lane >> 2, t = lane & 3;
    int wm = (warp >> 2) * 64;       // 0 or 64
    int wn = (warp & 3) * 64;        // 0..192
    int m0 = blockIdx.y * 128, n0 = blockIdx.x * 256;

    const float* Ag = A + (size_t)m0 * K;
    const float* Wg = W + n0;

    float acc[4][8][4];
#pragma unroll
    for (int a = 0; a < 4; a++)
#pragma unroll
        for (int b = 0; b < 8; b++)
#pragma unroll
            for (int c = 0; c < 4; c++) acc[a][b][c] = 0.f;

    // async tile loaders
    auto loadA = [&](int buf, int k0) {
        float* dst = Asb + buf * AS_SZ;
#pragma unroll
        for (int p = 0; p < 4; p++) {
            int idx = tid + p * 256;
            int r = idx >> 3, c = (idx & 7) << 2;
            CPA16(cvta_s(dst + r * AS_LD + c), Ag + (size_t)r * K + k0 + c);
        }
    };
    auto loadW = [&](int buf, int k0) {
        float* dst = Wsb + buf * WS_SZ;
#pragma unroll
        for (int p = 0; p < 8; p++) {
            int idx = tid + p * 256;
            int r = idx >> 6, c = (idx & 63) << 2;
            CPA16(cvta_s(dst + r * WS_LD + c), Wg + (size_t)(k0 + r) * Nc + c);
        }
    };

    int niter = K / 32;
    loadA(0, 0); loadW(0, 0); CPCOMMIT();

    for (int it = 0; it < niter; it++) {
        if (it + 1 < niter) {
            loadA((it + 1) & 1, (it + 1) * 32);
            loadW((it + 1) & 1, (it + 1) * 32);
            CPCOMMIT();
            CPWAIT1();
        } else {
            CPWAIT0();
        }
        __syncthreads();
        const float* As = Asb + (it & 1) * AS_SZ;
        const float* Ws = Wsb + (it & 1) * WS_SZ;

#pragma unroll
        for (int kk = 0; kk < 32; kk += 8) {
            float af[4][4], bf[8][2];
#pragma unroll
            for (int mt = 0; mt < 4; mt++) {
                int r = wm + mt * 16 + g;
                af[mt][0] = tf32r(As[r * AS_LD + kk + t]);
                af[mt][1] = tf32r(As[(r + 8) * AS_LD + kk + t]);
                af[mt][2] = tf32r(As[r * AS_LD + kk + t + 4]);
                af[mt][3] = tf32r(As[(r + 8) * AS_LD + kk + t + 4]);
            }
#pragma unroll
            for (int nt = 0; nt < 8; nt++) {
                int c = wn + nt * 8 + g;
                bf[nt][0] = tf32r(Ws[(kk + t) * WS_LD + c]);
                bf[nt][1] = tf32r(Ws[(kk + t + 4) * WS_LD + c]);
            }
#pragma unroll
            for (int mt = 0; mt < 4; mt++)
#pragma unroll
                for (int nt = 0; nt < 8; nt++)
                    mma8(acc[mt][nt][0], acc[mt][nt][1],
                         acc[mt][nt][2], acc[mt][nt][3],
                         af[mt][0], af[mt][1], af[mt][2], af[mt][3],
                         bf[nt][0], bf[nt][1]);
        }
        __syncthreads();
    }

    // epilogue
#pragma unroll
    for (int mt = 0; mt < 4; mt++) {
        int row = m0 + wm + mt * 16 + g;
#pragma unroll
        for (int nt = 0; nt < 8; nt++) {
            int col = n0 + wn + nt * 8 + 2 * t;
            float v0 = acc[mt][nt][0], v1 = acc[mt][nt][1];
            float v2 = acc[mt][nt][2], v3 = acc[mt][nt][3];
            if (EPI == 1 || EPI == 2 || EPI == 4) {
                float b0 = bias[col], b1 = bias[col + 1];
                v0 += b0; v1 += b1; v2 += b0; v3 += b1;
            }
            if (EPI == 2) {
                v0 = 0.5f * v0 * (1.0f + erff(v0 * 0.70710678118654752f));
                v1 = 0.5f * v1 * (1.0f + erff(v1 * 0.70710678118654752f));
                v2 = 0.5f * v2 * (1.0f + erff(v2 * 0.70710678118654752f));
                v3 = 0.5f * v3 * (1.0f + erff(v3 * 0.70710678118654752f));
            }
            size_t o0 = (size_t)row * Nc + col;
            size_t o1 = (size_t)(row + 8) * Nc + col;
            if (EPI == 3 || EPI == 4) {
                float2 r0 = *(const float2*)(res + o0);
                float2 r1 = *(const float2*)(res + o1);
                v0 += r0.x; v1 += r0.y; v2 += r1.x; v3 += r1.y;
            }
            *(float2*)(C + o0) = make_float2(v0, v1);
            *(float2*)(C + o1) = make_float2(v2, v3);
        }
    }
}

// ---------------- QK RMSNorm + 2D RoPE (one warp per (b,n,h) row) ----------
__global__ void __launch_bounds__(256) qkrope_k(float* __restrict__ Q,
                                                float* __restrict__ KV,
                                                const float* __restrict__ qg,
                                                const float* __restrict__ kg,
                                                const int* __restrict__ h_idx,
                                                const int* __restrict__ w_idx)
{
    int warp = blockIdx.x * 8 + (threadIdx.x >> 5);
    int lane = threadIdx.x & 31;
    int which = (warp >= Mrows * Hh) ? 1 : 0;        // 0 = Q, 1 = K
    int rid = which ? warp - Mrows * Hh : warp;
    int bn = rid / Hh;
    int h  = rid % Hh;
    float* ptr;
    const float* g;
    if (!which) { ptr = Q  + (size_t)bn * DIMd   + h * DHd; g = qg + h * DHd; }
    else        { ptr = KV + (size_t)bn * 2*DIMd + h * DHd; g = kg + h * DHd; }

    float v1 = ptr[lane], v2 = ptr[lane + 32];
    float ss = v1 * v1 + v2 * v2;
#pragma unroll
    for (int o = 16; o; o >>= 1) ss += __shfl_xor_sync(~0u, ss, o);
    float sc = 8.0f / fmaxf(sqrtf(ss), 1e-12f);
    v1 = v1 * sc * g[lane];
    v2 = v2 * sc * g[lane + 32];

    int f = lane & 15;
    float invf = exp2f(-(float)f * (13.287712379549449f / 16.0f));
    float th1 = (float)h_idx[bn] * invf;
    float th2 = (float)w_idx[bn] * invf;
    float p1 = __shfl_xor_sync(~0u, v1, 16);
    float p2 = __shfl_xor_sync(~0u, v2, 16);
    float rh1 = (lane < 16) ? -p1 : p1;
    float rh2 = (lane < 16) ? -p2 : p2;
    ptr[lane]      = v1 * cosf(th1) + rh1 * sinf(th1);
    ptr[lane + 32] = v2 * cosf(th2) + rh2 * sinf(th2);
}

// ---------------- TF32 tensor-core flash attention -------------------------
// CTA: 128 q rows, 4 warps (32 q rows each), 64-key tiles, dh=64.
#define QS_LD 68   // Qs/Ps row stride: frag banks (4g+t) distinct
#define KS_LD 68   // Ks as B-frag: banks (32nt+4g+t) distinct
#define VS_LD 72   // Vs as B-frag: banks (8t+g) distinct
#define ATT_SMEM ((128*QS_LD + 64*KS_LD + 64*VS_LD + 128*QS_LD) * 4)

__global__ void __launch_bounds__(128) attn_tc(const float* __restrict__ Q,
                                               const float* __restrict__ KV,
                                               const int* __restrict__ lengths,
                                               float* __restrict__ O)
{
    extern __shared__ float sm[];
    float* Qs = sm;                      // [128][QS_LD]
    float* Ks = Qs + 128 * QS_LD;        // [64][KS_LD]
    float* Vs = Ks + 64 * KS_LD;         // [64][VS_LD]
    float* Ps = Vs + 64 * VS_LD;         // [128][QS_LD]

    int b = blockIdx.z, h = blockIdx.y, q0 = blockIdx.x * 128;
    int tid = threadIdx.x;
    int warp = tid >> 5, lane = tid & 31;
    int g = lane >> 2, t = lane & 3;
    int wq = warp * 32;

    const float* Qg = Q  + ((size_t)b * Nn + q0) * DIMd + h * DHd;  // stride 768
    const float* Kg = KV + ((size_t)b * Nn) * 2 * DIMd + h * DHd;   // stride 1536
    int len = lengths[b];

    // load Q tile [128][64]
#pragma unroll
    for (int p = 0; p < 16; p++) {
        int idx = tid + p * 128;
        int r = idx >> 4, c = (idx & 15) << 2;
        float4 v = *(const float4*)(Qg + (size_t)r * DIMd + c);
        *(float4*)&Qs[r * QS_LD + c] = v;
    }

    float Oa[2][8][4];
    float mrow[2][2], lrow[2][2];
#pragma unroll
    for (int a = 0; a < 2; a++) {
#pragma unroll
        for (int n = 0; n < 8; n++)
#pragma unroll
            for (int c = 0; c < 4; c++) Oa[a][n][c] = 0.f;
        mrow[a][0] = mrow[a][1] = -1e30f;
        lrow[a][0] = lrow[a][1] = 0.f;
    }

    int ntiles = (len + 63) >> 6;
    for (int kt = 0; kt < ntiles; kt++) {
        __syncthreads();   // protect Ks/Vs/Ps reuse
        // load K,V tiles (64x64 each)
#pragma unroll
        for (int p = 0; p < 8; p++) {
            int idx = tid + p * 128;
            int r = idx >> 4, c = (idx & 15) << 2;
            const float* kp = Kg + (size_t)(kt * 64 + r) * (2 * DIMd) + c;
            *(float4*)&Ks[r * KS_LD + c] = *(const float4*)kp;
            *(float4*)&Vs[r * VS_LD + c] = *(const float4*)(kp + DIMd);
        }
        __syncthreads();

        // S = Q K^T  (k-dim = dh = 64)
        float S[2][8][4];
#pragma unroll
        for (int a = 0; a < 2; a++)
#pragma unroll
            for (int n = 0; n < 8; n++)
#pragma unroll
                for (int c = 0; c < 4; c++) S[a][n][c] = 0.f;

#pragma unroll
        for (int kk = 0; kk < 64; kk += 8) {
            float af[2][4], bf[8][2];
#pragma unroll
            for (int mt = 0; mt < 2; mt++) {
                int r = wq + mt * 16 + g;
                af[mt][0] = tf32r(Qs[r * QS_LD + kk + t]);
                af[mt][1] = tf32r(Qs[(r + 8) * QS_LD + kk + t]);
                af[mt][2] = tf32r(Qs[r * QS_LD + kk + t + 4]);
                af[mt][3] = tf32r(Qs[(r + 8) * QS_LD + kk + t + 4]);
            }
#pragma unroll
            for (int nt = 0; nt < 8; nt++) {
                int key = nt * 8 + g;
                bf[nt][0] = tf32r(Ks[key * KS_LD + kk + t]);
                bf[nt][1] = tf32r(Ks[key * KS_LD + kk + t + 4]);
            }
#pragma unroll
            for (int mt = 0; mt < 2; mt++)
#pragma unroll
                for (int nt = 0; nt < 8; nt++)
                    mma8(S[mt][nt][0], S[mt][nt][1], S[mt][nt][2], S[mt][nt][3],
                         af[mt][0], af[mt][1], af[mt][2], af[mt][3],
                         bf[nt][0], bf[nt][1]);
        }

        // key mask
#pragma unroll
        for (int nt = 0; nt < 8; nt++) {
            int kc = kt * 64 + nt * 8 + 2 * t;
            if (kc >= len) {
#pragma unroll
                for (int mt = 0; mt < 2; mt++) { S[mt][nt][0] = -1e30f; S[mt][nt][2] = -1e30f; }
            }
            if (kc + 1 >= len) {
#pragma unroll
                for (int mt = 0; mt < 2; mt++) { S[mt][nt][1] = -1e30f; S[mt][nt][3] = -1e30f; }
            }
        }

        // online softmax (per row; rows owned by lane-quads, reduce over t)
#pragma unroll
        for (int mt = 0; mt < 2; mt++) {
#pragma unroll
            for (int half = 0; half < 2; half++) {
                int i0 = half * 2, i1 = half * 2 + 1;
                float rm = -1e30f;
#pragma unroll
                for (int nt = 0; nt < 8; nt++)
                    rm = fmaxf(rm, fmaxf(S[mt][nt][i0], S[mt][nt][i1]));
                rm = fmaxf(rm, __shfl_xor_sync(~0u, rm, 1));
                rm = fmaxf(rm, __shfl_xor_sync(~0u, rm, 2));
                float mn = fmaxf(mrow[mt][half], rm);
                float rs = 0.f;
#pragma unroll
                for (int nt = 0; nt < 8; nt++) {
                    S[mt][nt][i0] = __expf(S[mt][nt][i0] - mn);
                    S[mt][nt][i1] = __expf(S[mt][nt][i1] - mn);
                    rs += S[mt][nt][i0] + S[mt][nt][i1];
                }
                rs += __shfl_xor_sync(~0u, rs, 1);
                rs += __shfl_xor_sync(~0u, rs, 2);
                float corr = __expf(mrow[mt][half] - mn);
                lrow[mt][half] = lrow[mt][half] * corr + rs;
                mrow[mt][half] = mn;
#pragma unroll
                for (int nt = 0; nt < 8; nt++) {
                    Oa[mt][nt][i0] *= corr;
                    Oa[mt][nt][i1] *= corr;
                }
            }
        }

        // stage P into smem (C-frag layout -> row-major)
#pragma unroll
        for (int mt = 0; mt < 2; mt++) {
            int r = wq + mt * 16 + g;
#pragma unroll
            for (int nt = 0; nt < 8; nt++) {
                int c = nt * 8 + 2 * t;
                *(float2*)&Ps[r * QS_LD + c]       = make_float2(S[mt][nt][0], S[mt][nt][1]);
                *(float2*)&Ps[(r + 8) * QS_LD + c] = make_float2(S[mt][nt][2], S[mt][nt][3]);
            }
        }
        __syncthreads();

        // O += P V  (k-dim = 64 keys)
#pragma unroll
        for (int kk = 0; kk < 64; kk += 8) {
            float af[2][4], bf[8][2];
#pragma unroll
            for (int mt = 0; mt < 2; mt++) {
                int r = wq + mt * 16 + g;
                af[mt][0] = tf32r(Ps[r * QS_LD + kk + t]);
                af[mt][1] = tf32r(Ps[(r + 8) * QS_LD + kk + t]);
                af[mt][2] = tf32r(Ps[r * QS_LD + kk + t + 4]);
                af[mt][3] = tf32r(Ps[(r + 8) * QS_LD + kk + t + 4]);
            }
#pragma unroll
            for (int nt = 0; nt < 8; nt++) {
                int c = nt * 8 + g;
                bf[nt][0] = tf32r(Vs[(kk + t) * VS_LD + c]);
                bf[nt][1] = tf32r(Vs[(kk + t + 4) * VS_LD + c]);
            }
#pragma unroll
            for (int mt = 0; mt < 2; mt++)
#pragma unroll
                for (int nt = 0; nt < 8; nt++)
                    mma8(Oa[mt][nt][0], Oa[mt][nt][1], Oa[mt][nt][2], Oa[mt][nt][3],
                         af[mt][0], af[mt][1], af[mt][2], af[mt][3],
                         bf[nt][0], bf[nt][1]);
        }
    }

    // write out: O / l  -> [B,N,H*DH]
#pragma unroll
    for (int mt = 0; mt < 2; mt++) {
        int row0 = q0 + wq + mt * 16 + g;
        float inv0 = 1.0f / lrow[mt][0];
        float inv1 = 1.0f / lrow[mt][1];
#pragma unroll
        for (int nt = 0; nt < 8; nt++) {
            int col = h * DHd + nt * 8 + 2 * t;
            size_t o0 = ((size_t)b * Nn + row0) * DIMd + col;
            size_t o1 = ((size_t)b * Nn + row0 + 8) * DIMd + col;
            *(float2*)&O[o0] = make_float2(Oa[mt][nt][0] * inv0, Oa[mt][nt][1] * inv0);
            *(float2*)&O[o1] = make_float2(Oa[mt][nt][2] * inv1, Oa[mt][nt][3] * inv1);
        }
    }
}

// ---------------- mask tail writer -----------------------------------------
__global__ void mask_k(const int* __restrict__ lengths, float* __restrict__ out)
{
    int i = blockIdx.x * blockDim.x + threadIdx.x;
    if (i < Bb * Nn) {
        int b = i / Nn, n = i % Nn;
        out[i] = (n < lengths[b]) ? 1.0f : 0.0f;
    }
}

// ---------------- host orchestration ---------------------------------------
extern "C" void kernel_launch(void* const* d_in, const int* in_sizes, int n_in,
                              void* d_out, int out_size)
{
    const float* patches    = (const float*)d_in[0];
    const float* pe_ln1_g   = (const float*)d_in[1];
    const float* pe_W       = (const float*)d_in[2];
    const float* pe_b       = (const float*)d_in[3];
    const float* pe_ln2_g   = (const float*)d_in[4];
    const float* attn_ln_g  = (const float*)d_in[5];
    const float* qn_g       = (const float*)d_in[6];
    const float* kn_g       = (const float*)d_in[7];
    const float* Wq         = (const float*)d_in[8];
    const float* Wkv        = (const float*)d_in[9];
    const float* Wo         = (const float*)d_in[10];
    const float* ff_ln_g    = (const float*)d_in[11];
    const float* W1         = (const float*)d_in[12];
    const float* b1         = (const float*)d_in[13];
    const float* W2         = (const float*)d_in[14];
    const float* b2         = (const float*)d_in[15];
    const float* final_ln_g = (const float*)d_in[16];
    const int*   h_idx      = (const int*)d_in[17];
    const int*   w_idx      = (const int*)d_in[18];
    const int*   lengths    = (const int*)d_in[19];

    float *x, *xn, *q, *kv, *ao, *hb;
    cudaGetSymbolAddress((void**)&x,  g_x);
    cudaGetSymbolAddress((void**)&xn, g_xn);
    cudaGetSymbolAddress((void**)&q,  g_q);
    cudaGetSymbolAddress((void**)&kv, g_kv);
    cudaGetSymbolAddress((void**)&ao, g_ao);
    cudaGetSymbolAddress((void**)&hb, g_h);

    const int GEMM_SMEM = (2 * AS_SZ + 2 * WS_SZ) * (int)sizeof(float);  // 104448
    cudaFuncSetAttribute(gemm_tc<0>, cudaFuncAttributeMaxDynamicSharedMemorySize, GEMM_SMEM);
    cudaFuncSetAttribute(gemm_tc<1>, cudaFuncAttributeMaxDynamicSharedMemorySize, GEMM_SMEM);
    cudaFuncSetAttribute(gemm_tc<2>, cudaFuncAttributeMaxDynamicSharedMemorySize, GEMM_SMEM);
    cudaFuncSetAttribute(gemm_tc<3>, cudaFuncAttributeMaxDynamicSharedMemorySize, GEMM_SMEM);
    cudaFuncSetAttribute(gemm_tc<4>, cudaFuncAttributeMaxDynamicSharedMemorySize, GEMM_SMEM);
    cudaFuncSetAttribute(attn_tc, cudaFuncAttributeMaxDynamicSharedMemorySize, ATT_SMEM);

    dim3 t256(256), t128(128);
    dim3 gN768(DIMd / 256, Mrows / 128);       // (3, 64)
    dim3 gN1536(2 * DIMd / 256, Mrows / 128);  // (6, 64)
    dim3 gN3072(MLPm / 256, Mrows / 128);      // (12, 64)

    // patch embedding: LN -> Linear+bias -> LN
    ln_k<<<Mrows, t256>>>(patches, pe_ln1_g, xn);
    gemm_tc<1><<<gN768, t256, GEMM_SMEM>>>(xn, pe_W, pe_b, nullptr, x, DIMd, DIMd);
    ln_k<<<Mrows, t256>>>(x, pe_ln2_g, x);

    for (int i = 0; i < Ll; i++) {
        ln_k<<<Mrows, t256>>>(x, attn_ln_g + (size_t)i * DIMd, xn);
        gemm_tc<0><<<gN768, t256, GEMM_SMEM>>>(xn, Wq + (size_t)i * DIMd * DIMd,
                                               nullptr, nullptr, q, DIMd, DIMd);
        gemm_tc<0><<<gN1536, t256, GEMM_SMEM>>>(xn, Wkv + (size_t)i * DIMd * 2 * DIMd,
                                                nullptr, nullptr, kv, DIMd, 2 * DIMd);
        qkrope_k<<<(2 * Mrows * Hh) / 8, t256>>>(
            q, kv, qn_g + (size_t)i * Hh * DHd, kn_g + (size_t)i * Hh * DHd,
            h_idx, w_idx);
        attn_tc<<<dim3(Nn / 128, Hh, Bb), t128, ATT_SMEM>>>(q, kv, lengths, ao);
        gemm_tc<3><<<gN768, t256, GEMM_SMEM>>>(ao, Wo + (size_t)i * DIMd * DIMd,
                                               nullptr, x, x, DIMd, DIMd);
        ln_k<<<Mrows, t256>>>(x, ff_ln_g + (size_t)i * DIMd, xn);
        gemm_tc<2><<<gN3072, t256, GEMM_SMEM>>>(xn, W1 + (size_t)i * DIMd * MLPm,
                                                b1 + (size_t)i * MLPm, nullptr, hb,
                                                DIMd, MLPm);
        gemm_tc<4><<<gN768, t256, GEMM_SMEM>>>(hb, W2 + (size_t)i * MLPm * DIMd,
                                               b2 + (size_t)i * DIMd, x, x, MLPm, DIMd);
    }

    ln_k<<<Mrows, t256>>>(x, final_ln_g, (float*)d_out);

    if (out_size > Mrows * DIMd) {
        mask_k<<<(Bb * Nn + 255) / 256, t256>>>(lengths,
                                                (float*)d_out + (size_t)Mrows * DIMd);
    }
}

// round 5
// speedup vs baseline: 2.9405x; 1.0320x over previous
#include <cuda_runtime.h>
#include <cuda_bf16.h>
#include <math.h>

// Problem dims
#define Bb   4
#define Nn   2048
#define DIMd 768
#define Hh   12
#define DHd  64
#define MLPm 3072
#define Ll   2
#define Mrows (Bb*Nn)   // 8192

// ---------------- scratch (device globals: allocation-free) ----------------
__device__ float g_x [Mrows*DIMd];
__device__ float g_xn[Mrows*DIMd];
__device__ float g_q [Mrows*DIMd];
__device__ float g_kv[Mrows*2*DIMd];
__device__ float g_ao[Mrows*DIMd];
__device__ float g_h [Mrows*MLPm];
// packed+tf32-rounded weights: pe_W + 2x(Wq,Wkv,Wo,W1,W2)
#define WPK_PE   0
#define WPK_LAYER (DIMd*DIMd + DIMd*2*DIMd + DIMd*DIMd + DIMd*MLPm + MLPm*DIMd)
__device__ float g_wpk[DIMd*DIMd + 2*WPK_LAYER];

// ---------------- PTX helpers ----------------------------------------------
__device__ __forceinline__ unsigned cvta_s(const void* p) {
    return (unsigned)__cvta_generic_to_shared(p);
}
#define CPA16(dst, src) asm volatile("cp.async.cg.shared.global [%0], [%1], 16;" :: "r"(dst), "l"(src))
#define CPCOMMIT()      asm volatile("cp.async.commit_group;")
#define CPWAIT1()       asm volatile("cp.async.wait_group 1;")
#define CPWAIT0()       asm volatile("cp.async.wait_group 0;")

__device__ __forceinline__ float tf32r(float x) {
    float r;
    asm("cvt.rna.tf32.f32 %0, %1;" : "=f"(r) : "f"(x));
    return r;
}

__device__ __forceinline__ void mma8(float& c0, float& c1, float& c2, float& c3,
                                     float a0, float a1, float a2, float a3,
                                     float b0, float b1) {
    asm volatile(
        "mma.sync.aligned.m16n8k8.row.col.f32.tf32.tf32.f32 "
        "{%0,%1,%2,%3},{%4,%5,%6,%7},{%8,%9},{%0,%1,%2,%3};"
        : "+f"(c0), "+f"(c1), "+f"(c2), "+f"(c3)
        : "r"(__float_as_uint(a0)), "r"(__float_as_uint(a1)),
          "r"(__float_as_uint(a2)), "r"(__float_as_uint(a3)),
          "r"(__float_as_uint(b0)), "r"(__float_as_uint(b1)));
}

// ---------------- weight pack: round to tf32 + B-fragment layout -----------
// Packed element: P[((k0/32)*(Nc/8)+ntg)*256 + kkd*64 + lane*2 + half]
//   = tf32(W[k0 + kkd*8 + (lane&3) + half*4][ntg*8 + (lane>>2)])
__global__ void __launch_bounds__(256) pack_w(const float* __restrict__ W,
                                              float* __restrict__ P,
                                              int K, int Nc)
{
    __shared__ float Ws[32][257];
    int tid = threadIdx.x;
    int n0 = blockIdx.x * 256, k0 = blockIdx.y * 32;
#pragma unroll
    for (int p = 0; p < 8; p++) {
        int idx = tid + p * 256;         // float4 id over 32x256
        int r = idx >> 6, c4 = (idx & 63) << 2;
        float4 v = *(const float4*)(W + (size_t)(k0 + r) * Nc + n0 + c4);
        Ws[r][c4] = v.x; Ws[r][c4 + 1] = v.y;
        Ws[r][c4 + 2] = v.z; Ws[r][c4 + 3] = v.w;
    }
    __syncthreads();
    float* out = P + ((size_t)(k0 >> 5) * (Nc >> 3) + (n0 >> 3)) * 256;
#pragma unroll
    for (int p = 0; p < 8; p++) {
        int q = tid + p * 256;           // float4 id in [0,2048)
        int ntg = q >> 6;
        int r = q & 63;
        int kkd = r >> 4;
        int f0 = (r & 15) << 2;          // first float index in 64-block
        int L0 = f0 >> 1;                // lane of first pair
        int t0 = L0 & 3, g = L0 >> 2;
        int c = ntg * 8 + g;
        float4 o;
        o.x = tf32r(Ws[kkd * 8 + t0    ][c]);
        o.y = tf32r(Ws[kkd * 8 + t0 + 4][c]);
        o.z = tf32r(Ws[kkd * 8 + t0 + 1][c]);
        o.w = tf32r(Ws[kkd * 8 + t0 + 5][c]);
        *(float4*)(out + (size_t)q * 4) = o;
    }
}

// ---------------- LayerNorm (ROUND: tf32-round output for GEMM A) ----------
template<int ROUND>
__global__ void __launch_bounds__(256) ln_k(const float* __restrict__ X,
                                            const float* __restrict__ g,
                                            float* __restrict__ Y)
{
    int row = blockIdx.x;
    const float* x = X + (size_t)row * DIMd;
    int tid = threadIdx.x;
    float v[3]; float s = 0.f, sq = 0.f;
#pragma unroll
    for (int i = 0; i < 3; i++) {
        v[i] = x[tid + i * 256];
        s += v[i]; sq += v[i] * v[i];
    }
#pragma unroll
    for (int o = 16; o; o >>= 1) {
        s  += __shfl_xor_sync(~0u, s, o);
        sq += __shfl_xor_sync(~0u, sq, o);
    }
    __shared__ float red[2][8];
    int w = tid >> 5, lane = tid & 31;
    if (lane == 0) { red[0][w] = s; red[1][w] = sq; }
    __syncthreads();
    s = 0.f; sq = 0.f;
#pragma unroll
    for (int j = 0; j < 8; j++) { s += red[0][j]; sq += red[1][j]; }
    float mean = s * (1.f / DIMd);
    float var  = sq * (1.f / DIMd) - mean * mean;
    float rstd = rsqrtf(var + 1e-5f);
    float* y = Y + (size_t)row * DIMd;
#pragma unroll
    for (int i = 0; i < 3; i++) {
        int c = tid + i * 256;
        float o = (v[i] - mean) * rstd * g[c];
        y[c] = ROUND ? tf32r(o) : o;
    }
}

// ---------------- TF32 TC GEMM, packed B, 3-stage cp.async -----------------
// CTA 128x256, k-step 32, 8 warps of 64x64. A pre-rounded row-major,
// B pre-rounded fragment-packed. EPI: 0 none,1 +bias,2 gelu(x+b)(round out),
// 3 +res, 4 +bias+res
#define AS_LD 36
#define AS_SZ (128*AS_LD)     // 4608 floats
#define BS_SZ (32*256)        // 8192 floats
#define STG_SZ (AS_SZ + BS_SZ)
#define GEMM_SMEM (3*STG_SZ*4)   // 153600 B

template<int EPI>
__global__ void __launch_bounds__(256) gemm_tc(const float* __restrict__ A,
                                               const float* __restrict__ Wpk,
                                               const float* __restrict__ bias,
                                               const float* __restrict__ res,
                                               float* __restrict__ C,
                                               int K, int Nc)
{
    extern __shared__ float sm[];
    int tid = threadIdx.x;
    int warp = tid >> 5, lane = tid & 31;
    int g = lane >> 2, t = lane & 3;
    int wm = (warp >> 2) * 64;
    int warpn = warp & 3;
    int m0 = blockIdx.y * 128, n0 = blockIdx.x * 256;

    const float* Ag = A + (size_t)m0 * K;
    // packed W region for this CTA's n-slice at k-block kb:
    //   Wpk + ((kb*(Nc/8)) + n0/8)*256, contiguous 8192 floats
    const float* Wg = Wpk + (size_t)(n0 >> 3) * 256;
    size_t wstride = (size_t)(Nc >> 3) * 256;   // per k-block

    float acc[4][8][4];
#pragma unroll
    for (int a = 0; a < 4; a++)
#pragma unroll
        for (int b = 0; b < 8; b++)
#pragma unroll
            for (int c = 0; c < 4; c++) acc[a][b][c] = 0.f;

    auto loadA = [&](int buf, int k0) {
        float* dst = sm + buf * STG_SZ;
#pragma unroll
        for (int p = 0; p < 4; p++) {
            int idx = tid + p * 256;
            int r = idx >> 3, c = (idx & 7) << 2;
            CPA16(cvta_s(dst + r * AS_LD + c), Ag + (size_t)r * K + k0 + c);
        }
    };
    auto loadW = [&](int buf, int kb) {
        float* dst = sm + buf * STG_SZ + AS_SZ;
        const float* src = Wg + (size_t)kb * wstride;
#pragma unroll
        for (int p = 0; p < 8; p++) {
            int gi = tid + p * 256;
            CPA16(cvta_s(dst + gi * 4), src + (size_t)gi * 4);
        }
    };

    int niter = K / 32;
    loadA(0, 0); loadW(0, 0); CPCOMMIT();
    loadA(1, 32); loadW(1, 1); CPCOMMIT();

    for (int it = 0; it < niter; it++) {
        if (it + 1 < niter) { CPWAIT1(); } else { CPWAIT0(); }
        __syncthreads();
        if (it + 2 < niter) {
            loadA((it + 2) % 3, (it + 2) * 32);
            loadW((it + 2) % 3, it + 2);
            CPCOMMIT();
        }
        const float* As = sm + (it % 3) * STG_SZ;
        const float* Bs = As + AS_SZ;

#pragma unroll
        for (int kkd = 0; kkd < 4; kkd++) {
            float af[4][4], bf[8][2];
#pragma unroll
            for (int mt = 0; mt < 4; mt++) {
                int r = wm + mt * 16 + g;
                af[mt][0] = As[r * AS_LD + kkd * 8 + t];
                af[mt][1] = As[(r + 8) * AS_LD + kkd * 8 + t];
                af[mt][2] = As[r * AS_LD + kkd * 8 + t + 4];
                af[mt][3] = As[(r + 8) * AS_LD + kkd * 8 + t + 4];
            }
#pragma unroll
            for (int nt = 0; nt < 8; nt++) {
                float2 bb = *(const float2*)&Bs[((warpn * 8 + nt) * 4 + kkd) * 64 + lane * 2];
                bf[nt][0] = bb.x; bf[nt][1] = bb.y;
            }
#pragma unroll
            for (int mt = 0; mt < 4; mt++)
#pragma unroll
                for (int nt = 0; nt < 8; nt++)
                    mma8(acc[mt][nt][0], acc[mt][nt][1],
                         acc[mt][nt][2], acc[mt][nt][3],
                         af[mt][0], af[mt][1], af[mt][2], af[mt][3],
                         bf[nt][0], bf[nt][1]);
        }
        __syncthreads();
    }

    int wn = warpn * 64;
#pragma unroll
    for (int mt = 0; mt < 4; mt++) {
        int row = m0 + wm + mt * 16 + g;
#pragma unroll
        for (int nt = 0; nt < 8; nt++) {
            int col = n0 + wn + nt * 8 + 2 * t;
            float v0 = acc[mt][nt][0], v1 = acc[mt][nt][1];
            float v2 = acc[mt][nt][2], v3 = acc[mt][nt][3];
            if (EPI == 1 || EPI == 2 || EPI == 4) {
                float b0 = bias[col], b1 = bias[col + 1];
                v0 += b0; v1 += b1; v2 += b0; v3 += b1;
            }
            if (EPI == 2) {
                v0 = tf32r(0.5f * v0 * (1.0f + erff(v0 * 0.70710678118654752f)));
                v1 = tf32r(0.5f * v1 * (1.0f + erff(v1 * 0.70710678118654752f)));
                v2 = tf32r(0.5f * v2 * (1.0f + erff(v2 * 0.70710678118654752f)));
                v3 = tf32r(0.5f * v3 * (1.0f + erff(v3 * 0.70710678118654752f)));
            }
            size_t o0 = (size_t)row * Nc + col;
            size_t o1 = (size_t)(row + 8) * Nc + col;
            if (EPI == 3 || EPI == 4) {
                float2 r0 = *(const float2*)(res + o0);
                float2 r1 = *(const float2*)(res + o1);
                v0 += r0.x; v1 += r0.y; v2 += r1.x; v3 += r1.y;
            }
            *(float2*)(C + o0) = make_float2(v0, v1);
            *(float2*)(C + o1) = make_float2(v2, v3);
        }
    }
}

// -------- QK RMSNorm + 2D RoPE + tf32 round (also rounds V) ---------------
__global__ void __launch_bounds__(256) qkrope_k(float* __restrict__ Q,
                                                float* __restrict__ KV,
                                                const float* __restrict__ qg,
                                                const float* __restrict__ kg,
                                                const int* __restrict__ h_idx,
                                                const int* __restrict__ w_idx)
{
    int warp = blockIdx.x * 8 + (threadIdx.x >> 5);
    int lane = threadIdx.x & 31;
    int grp = warp / (Mrows * Hh);       // 0=Q, 1=K, 2=V
    int rid = warp - grp * (Mrows * Hh);
    int bn = rid / Hh;
    int h  = rid % Hh;

    if (grp == 2) {  // V: round only
        float* ptr = KV + (size_t)bn * 2 * DIMd + DIMd + h * DHd;
        ptr[lane]      = tf32r(ptr[lane]);
        ptr[lane + 32] = tf32r(ptr[lane + 32]);
        return;
    }

    float* ptr;
    const float* g;
    if (grp == 0) { ptr = Q  + (size_t)bn * DIMd     + h * DHd; g = qg + h * DHd; }
    else          { ptr = KV + (size_t)bn * 2 * DIMd + h * DHd; g = kg + h * DHd; }

    float v1 = ptr[lane], v2 = ptr[lane + 32];
    float ss = v1 * v1 + v2 * v2;
#pragma unroll
    for (int o = 16; o; o >>= 1) ss += __shfl_xor_sync(~0u, ss, o);
    float sc = 8.0f / fmaxf(sqrtf(ss), 1e-12f);
    v1 = v1 * sc * g[lane];
    v2 = v2 * sc * g[lane + 32];

    int f = lane & 15;
    float invf = exp2f(-(float)f * (13.287712379549449f / 16.0f));
    float th1 = (float)h_idx[bn] * invf;
    float th2 = (float)w_idx[bn] * invf;
    float p1 = __shfl_xor_sync(~0u, v1, 16);
    float p2 = __shfl_xor_sync(~0u, v2, 16);
    float rh1 = (lane < 16) ? -p1 : p1;
    float rh2 = (lane < 16) ? -p2 : p2;
    ptr[lane]      = tf32r(v1 * cosf(th1) + rh1 * sinf(th1));
    ptr[lane + 32] = tf32r(v2 * cosf(th2) + rh2 * sinf(th2));
}

// ---------------- TF32 TC flash attention (pre-rounded inputs) -------------
#define QS_LD 68
#define KS_LD 68
#define VS_LD 72
#define ATT_SMEM ((128*QS_LD + 64*KS_LD + 64*VS_LD + 128*QS_LD) * 4)

__global__ void __launch_bounds__(128) attn_tc(const float* __restrict__ Q,
                                               const float* __restrict__ KV,
                                               const int* __restrict__ lengths,
                                               float* __restrict__ O)
{
    extern __shared__ float sm[];
    float* Qs = sm;
    float* Ks = Qs + 128 * QS_LD;
    float* Vs = Ks + 64 * KS_LD;
    float* Ps = Vs + 64 * VS_LD;

    int b = blockIdx.z, h = blockIdx.y, q0 = blockIdx.x * 128;
    int tid = threadIdx.x;
    int warp = tid >> 5, lane = tid & 31;
    int g = lane >> 2, t = lane & 3;
    int wq = warp * 32;

    const float* Qg = Q  + ((size_t)b * Nn + q0) * DIMd + h * DHd;
    const float* Kg = KV + ((size_t)b * Nn) * 2 * DIMd + h * DHd;
    int len = lengths[b];

#pragma unroll
    for (int p = 0; p < 16; p++) {
        int idx = tid + p * 128;
        int r = idx >> 4, c = (idx & 15) << 2;
        float4 v = *(const float4*)(Qg + (size_t)r * DIMd + c);
        *(float4*)&Qs[r * QS_LD + c] = v;
    }

    float Oa[2][8][4];
    float mrow[2][2], lrow[2][2];
#pragma unroll
    for (int a = 0; a < 2; a++) {
#pragma unroll
        for (int n = 0; n < 8; n++)
#pragma unroll
            for (int c = 0; c < 4; c++) Oa[a][n][c] = 0.f;
        mrow[a][0] = mrow[a][1] = -1e30f;
        lrow[a][0] = lrow[a][1] = 0.f;
    }

    int ntiles = (len + 63) >> 6;
    for (int kt = 0; kt < ntiles; kt++) {
        __syncthreads();
#pragma unroll
        for (int p = 0; p < 8; p++) {
            int idx = tid + p * 128;
            int r = idx >> 4, c = (idx & 15) << 2;
            const float* kp = Kg + (size_t)(kt * 64 + r) * (2 * DIMd) + c;
            *(float4*)&Ks[r * KS_LD + c] = *(const float4*)kp;
            *(float4*)&Vs[r * VS_LD + c] = *(const float4*)(kp + DIMd);
        }
        __syncthreads();

        float S[2][8][4];
#pragma unroll
        for (int a = 0; a < 2; a++)
#pragma unroll
            for (int n = 0; n < 8; n++)
#pragma unroll
                for (int c = 0; c < 4; c++) S[a][n][c] = 0.f;

#pragma unroll
        for (int kk = 0; kk < 64; kk += 8) {
            float af[2][4], bf[8][2];
#pragma unroll
            for (int mt = 0; mt < 2; mt++) {
                int r = wq + mt * 16 + g;
                af[mt][0] = Qs[r * QS_LD + kk + t];
                af[mt][1] = Qs[(r + 8) * QS_LD + kk + t];
                af[mt][2] = Qs[r * QS_LD + kk + t + 4];
                af[mt][3] = Qs[(r + 8) * QS_LD + kk + t + 4];
            }
#pragma unroll
            for (int nt = 0; nt < 8; nt++) {
                int key = nt * 8 + g;
                bf[nt][0] = Ks[key * KS_LD + kk + t];
                bf[nt][1] = Ks[key * KS_LD + kk + t + 4];
            }
#pragma unroll
            for (int mt = 0; mt < 2; mt++)
#pragma unroll
                for (int nt = 0; nt < 8; nt++)
                    mma8(S[mt][nt][0], S[mt][nt][1], S[mt][nt][2], S[mt][nt][3],
                         af[mt][0], af[mt][1], af[mt][2], af[mt][3],
                         bf[nt][0], bf[nt][1]);
        }

#pragma unroll
        for (int nt = 0; nt < 8; nt++) {
            int kc = kt * 64 + nt * 8 + 2 * t;
            if (kc >= len) {
#pragma unroll
                for (int mt = 0; mt < 2; mt++) { S[mt][nt][0] = -1e30f; S[mt][nt][2] = -1e30f; }
            }
            if (kc + 1 >= len) {
#pragma unroll
                for (int mt = 0; mt < 2; mt++) { S[mt][nt][1] = -1e30f; S[mt][nt][3] = -1e30f; }
            }
        }

#pragma unroll
        for (int mt = 0; mt < 2; mt++) {
#pragma unroll
            for (int half = 0; half < 2; half++) {
                int i0 = half * 2, i1 = half * 2 + 1;
                float rm = -1e30f;
#pragma unroll
                for (int nt = 0; nt < 8; nt++)
                    rm = fmaxf(rm, fmaxf(S[mt][nt][i0], S[mt][nt][i1]));
                rm = fmaxf(rm, __shfl_xor_sync(~0u, rm, 1));
                rm = fmaxf(rm, __shfl_xor_sync(~0u, rm, 2));
                float mn = fmaxf(mrow[mt][half], rm);
                float rs = 0.f;
#pragma unroll
                for (int nt = 0; nt < 8; nt++) {
                    S[mt][nt][i0] = __expf(S[mt][nt][i0] - mn);
                    S[mt][nt][i1] = __expf(S[mt][nt][i1] - mn);
                    rs += S[mt][nt][i0] + S[mt][nt][i1];
                }
                rs += __shfl_xor_sync(~0u, rs, 1);
                rs += __shfl_xor_sync(~0u, rs, 2);
                float corr = __expf(mrow[mt][half] - mn);
                lrow[mt][half] = lrow[mt][half] * corr + rs;
                mrow[mt][half] = mn;
#pragma unroll
                for (int nt = 0; nt < 8; nt++) {
                    Oa[mt][nt][i0] *= corr;
                    Oa[mt][nt][i1] *= corr;
                }
            }
        }

        // stage P (round to tf32 here; loads below skip cvt)
#pragma unroll
        for (int mt = 0; mt < 2; mt++) {
            int r = wq + mt * 16 + g;
#pragma unroll
            for (int nt = 0; nt < 8; nt++) {
                int c = nt * 8 + 2 * t;
                *(float2*)&Ps[r * QS_LD + c] =
                    make_float2(tf32r(S[mt][nt][0]), tf32r(S[mt][nt][1]));
                *(float2*)&Ps[(r + 8) * QS_LD + c] =
                    make_float2(tf32r(S[mt][nt][2]), tf32r(S[mt][nt][3]));
            }
        }
        __syncthreads();

#pragma unroll
        for (int kk = 0; kk < 64; kk += 8) {
            float af[2][4], bf[8][2];
#pragma unroll
            for (int mt = 0; mt < 2; mt++) {
                int r = wq + mt * 16 + g;
                af[mt][0] = Ps[r * QS_LD + kk + t];
                af[mt][1] = Ps[(r + 8) * QS_LD + kk + t];
                af[mt][2] = Ps[r * QS_LD + kk + t + 4];
                af[mt][3] = Ps[(r + 8) * QS_LD + kk + t + 4];
            }
#pragma unroll
            for (int nt = 0; nt < 8; nt++) {
                int c = nt * 8 + g;
                bf[nt][0] = Vs[(kk + t) * VS_LD + c];
                bf[nt][1] = Vs[(kk + t + 4) * VS_LD + c];
            }
#pragma unroll
            for (int mt = 0; mt < 2; mt++)
#pragma unroll
                for (int nt = 0; nt < 8; nt++)
                    mma8(Oa[mt][nt][0], Oa[mt][nt][1], Oa[mt][nt][2], Oa[mt][nt][3],
                         af[mt][0], af[mt][1], af[mt][2], af[mt][3],
                         bf[nt][0], bf[nt][1]);
        }
    }

    // write out rounded (ao is only ever a GEMM A operand)
#pragma unroll
    for (int mt = 0; mt < 2; mt++) {
        int row0 = q0 + wq + mt * 16 + g;
        float inv0 = 1.0f / lrow[mt][0];
        float inv1 = 1.0f / lrow[mt][1];
#pragma unroll
        for (int nt = 0; nt < 8; nt++) {
            int col = h * DHd + nt * 8 + 2 * t;
            size_t o0 = ((size_t)b * Nn + row0) * DIMd + col;
            size_t o1 = ((size_t)b * Nn + row0 + 8) * DIMd + col;
            *(float2*)&O[o0] = make_float2(tf32r(Oa[mt][nt][0] * inv0),
                                           tf32r(Oa[mt][nt][1] * inv0));
            *(float2*)&O[o1] = make_float2(tf32r(Oa[mt][nt][2] * inv1),
                                           tf32r(Oa[mt][nt][3] * inv1));
        }
    }
}

// ---------------- mask tail writer -----------------------------------------
__global__ void mask_k(const int* __restrict__ lengths, float* __restrict__ out)
{
    int i = blockIdx.x * blockDim.x + threadIdx.x;
    if (i < Bb * Nn) {
        int b = i / Nn, n = i % Nn;
        out[i] = (n < lengths[b]) ? 1.0f : 0.0f;
    }
}

// ---------------- host orchestration ---------------------------------------
extern "C" void kernel_launch(void* const* d_in, const int* in_sizes, int n_in,
                              void* d_out, int out_size)
{
    const float* patches    = (const float*)d_in[0];
    const float* pe_ln1_g   = (const float*)d_in[1];
    const float* pe_W       = (const float*)d_in[2];
    const float* pe_b       = (const float*)d_in[3];
    const float* pe_ln2_g   = (const float*)d_in[4];
    const float* attn_ln_g  = (const float*)d_in[5];
    const float* qn_g       = (const float*)d_in[6];
    const float* kn_g       = (const float*)d_in[7];
    const float* Wq         = (const float*)d_in[8];
    const float* Wkv        = (const float*)d_in[9];
    const float* Wo         = (const float*)d_in[10];
    const float* ff_ln_g    = (const float*)d_in[11];
    const float* W1         = (const float*)d_in[12];
    const float* b1         = (const float*)d_in[13];
    const float* W2         = (const float*)d_in[14];
    const float* b2         = (const float*)d_in[15];
    const float* final_ln_g = (const float*)d_in[16];
    const int*   h_idx      = (const int*)d_in[17];
    const int*   w_idx      = (const int*)d_in[18];
    const int*   lengths    = (const int*)d_in[19];

    float *x, *xn, *q, *kv, *ao, *hb, *wpk;
    cudaGetSymbolAddress((void**)&x,   g_x);
    cudaGetSymbolAddress((void**)&xn,  g_xn);
    cudaGetSymbolAddress((void**)&q,   g_q);
    cudaGetSymbolAddress((void**)&kv,  g_kv);
    cudaGetSymbolAddress((void**)&ao,  g_ao);
    cudaGetSymbolAddress((void**)&hb,  g_h);
    cudaGetSymbolAddress((void**)&wpk, g_wpk);

    cudaFuncSetAttribute(gemm_tc<0>, cudaFuncAttributeMaxDynamicSharedMemorySize, GEMM_SMEM);
    cudaFuncSetAttribute(gemm_tc<1>, cudaFuncAttributeMaxDynamicSharedMemorySize, GEMM_SMEM);
    cudaFuncSetAttribute(gemm_tc<2>, cudaFuncAttributeMaxDynamicSharedMemorySize, GEMM_SMEM);
    cudaFuncSetAttribute(gemm_tc<3>, cudaFuncAttributeMaxDynamicSharedMemorySize, GEMM_SMEM);
    cudaFuncSetAttribute(gemm_tc<4>, cudaFuncAttributeMaxDynamicSharedMemorySize, GEMM_SMEM);
    cudaFuncSetAttribute(attn_tc, cudaFuncAttributeMaxDynamicSharedMemorySize, ATT_SMEM);

    dim3 t256(256), t128(128);

    // ---- weight pre-pass: tf32-round + fragment-pack -----------------------
    // offsets inside g_wpk (floats)
    size_t off_pe = WPK_PE;
    size_t off_q [Ll], off_kv[Ll], off_o[Ll], off_1[Ll], off_2[Ll];
    {
        size_t cur = DIMd * DIMd;
        for (int i = 0; i < Ll; i++) {
            off_q [i] = cur; cur += (size_t)DIMd * DIMd;
            off_kv[i] = cur; cur += (size_t)DIMd * 2 * DIMd;
            off_o [i] = cur; cur += (size_t)DIMd * DIMd;
            off_1 [i] = cur; cur += (size_t)DIMd * MLPm;
            off_2 [i] = cur; cur += (size_t)MLPm * DIMd;
        }
    }
    pack_w<<<dim3(DIMd / 256, DIMd / 32), t256>>>(pe_W, wpk + off_pe, DIMd, DIMd);
    for (int i = 0; i < Ll; i++) {
        pack_w<<<dim3(DIMd / 256, DIMd / 32), t256>>>(Wq  + (size_t)i * DIMd * DIMd,      wpk + off_q [i], DIMd, DIMd);
        pack_w<<<dim3(2 * DIMd / 256, DIMd / 32), t256>>>(Wkv + (size_t)i * DIMd * 2 * DIMd, wpk + off_kv[i], DIMd, 2 * DIMd);
        pack_w<<<dim3(DIMd / 256, DIMd / 32), t256>>>(Wo  + (size_t)i * DIMd * DIMd,      wpk + off_o [i], DIMd, DIMd);
        pack_w<<<dim3(MLPm / 256, DIMd / 32), t256>>>(W1  + (size_t)i * DIMd * MLPm,      wpk + off_1 [i], DIMd, MLPm);
        pack_w<<<dim3(DIMd / 256, MLPm / 32), t256>>>(W2  + (size_t)i * MLPm * DIMd,      wpk + off_2 [i], MLPm, DIMd);
    }

    dim3 gN768(DIMd / 256, Mrows / 128);
    dim3 gN1536(2 * DIMd / 256, Mrows / 128);
    dim3 gN3072(MLPm / 256, Mrows / 128);

    // patch embedding: LN -> Linear+bias -> LN
    ln_k<1><<<Mrows, t256>>>(patches, pe_ln1_g, xn);
    gemm_tc<1><<<gN768, t256, GEMM_SMEM>>>(xn, wpk + off_pe, pe_b, nullptr, x, DIMd, DIMd);
    ln_k<0><<<Mrows, t256>>>(x, pe_ln2_g, x);

    for (int i = 0; i < Ll; i++) {
        ln_k<1><<<Mrows, t256>>>(x, attn_ln_g + (size_t)i * DIMd, xn);
        gemm_tc<0><<<gN768, t256, GEMM_SMEM>>>(xn, wpk + off_q[i], nullptr, nullptr, q, DIMd, DIMd);
        gemm_tc<0><<<gN1536, t256, GEMM_SMEM>>>(xn, wpk + off_kv[i], nullptr, nullptr, kv, DIMd, 2 * DIMd);
        qkrope_k<<<(3 * Mrows * Hh) / 8, t256>>>(
            q, kv, qn_g + (size_t)i * Hh * DHd, kn_g + (size_t)i * Hh * DHd,
            h_idx, w_idx);
        attn_tc<<<dim3(Nn / 128, Hh, Bb), t128, ATT_SMEM>>>(q, kv, lengths, ao);
        gemm_tc<3><<<gN768, t256, GEMM_SMEM>>>(ao, wpk + off_o[i], nullptr, x, x, DIMd, DIMd);
        ln_k<1><<<Mrows, t256>>>(x, ff_ln_g + (size_t)i * DIMd, xn);
        gemm_tc<2><<<gN3072, t256, GEMM_SMEM>>>(xn, wpk + off_1[i], b1 + (size_t)i * MLPm, nullptr, hb, DIMd, MLPm);
        gemm_tc<4><<<gN768, t256, GEMM_SMEM>>>(hb, wpk + off_2[i], b2 + (size_t)i * DIMd, x, x, MLPm, DIMd);
    }

    ln_k<0><<<Mrows, t256>>>(x, final_ln_g, (float*)d_out);

    if (out_size > Mrows * DIMd) {
        mask_k<<<(Bb * Nn + 255) / 256, t256>>>(lengths,
                                                (float*)d_out + (size_t)Mrows * DIMd);
    }
}

// round 6
// speedup vs baseline: 3.8171x; 1.2981x over previous
#include <cuda_runtime.h>
#include <cuda_bf16.h>
#include <math.h>

// Problem dims
#define Bb   4
#define Nn   2048
#define DIMd 768
#define Hh   12
#define DHd  64
#define MLPm 3072
#define Ll   2
#define Mrows (Bb*Nn)   // 8192

// ---------------- scratch (device globals: allocation-free) ----------------
__device__ float g_x [Mrows*DIMd];
__device__ float g_xn[Mrows*DIMd];
__device__ float g_q [Mrows*DIMd];
__device__ float g_kv[Mrows*2*DIMd];
__device__ float g_ao[Mrows*DIMd];
__device__ float g_h [Mrows*MLPm];
#define WPK_LAYER (DIMd*DIMd + DIMd*2*DIMd + DIMd*DIMd + DIMd*MLPm + MLPm*DIMd)
__device__ float g_wpk[DIMd*DIMd + 2*WPK_LAYER];

// ---------------- PTX helpers ----------------------------------------------
__device__ __forceinline__ unsigned cvta_s(const void* p) {
    return (unsigned)__cvta_generic_to_shared(p);
}
#define CPA16(dst, src) asm volatile("cp.async.cg.shared.global [%0], [%1], 16;" :: "r"(dst), "l"(src))
#define CPCOMMIT()      asm volatile("cp.async.commit_group;")
#define CPWAIT1()       asm volatile("cp.async.wait_group 1;")
#define CPWAIT0()       asm volatile("cp.async.wait_group 0;")

__device__ __forceinline__ float tf32r(float x) {
    float r;
    asm("cvt.rna.tf32.f32 %0, %1;" : "=f"(r) : "f"(x));
    return r;
}

__device__ __forceinline__ void mma8(float& c0, float& c1, float& c2, float& c3,
                                     float a0, float a1, float a2, float a3,
                                     float b0, float b1) {
    asm volatile(
        "mma.sync.aligned.m16n8k8.row.col.f32.tf32.tf32.f32 "
        "{%0,%1,%2,%3},{%4,%5,%6,%7},{%8,%9},{%0,%1,%2,%3};"
        : "+f"(c0), "+f"(c1), "+f"(c2), "+f"(c3)
        : "r"(__float_as_uint(a0)), "r"(__float_as_uint(a1)),
          "r"(__float_as_uint(a2)), "r"(__float_as_uint(a3)),
          "r"(__float_as_uint(b0)), "r"(__float_as_uint(b1)));
}

// ---------------- single-launch weight pack --------------------------------
// Packed element: P[((k0/32)*(Nc/8)+ntg)*256 + kkd*64 + lane*2 + half]
//   = tf32(W[k0 + kkd*8 + (lane&3) + half*4][ntg*8 + (lane>>2)])
struct PackDesc { const float* src; float* dst; int K; int Nc; };
struct PackTable { PackDesc d[11]; };

__global__ void __launch_bounds__(256) pack_all(PackTable tab)
{
    __shared__ float Ws[32][257];
    PackDesc pd = tab.d[blockIdx.y];
    int tx = pd.Nc >> 8;                  // tiles in n
    int total = tx * (pd.K >> 5);
    int bx = blockIdx.x;
    if (bx >= total) return;
    int n0 = (bx % tx) << 8, k0 = (bx / tx) << 5;
    const float* W = pd.src;
    int Nc = pd.Nc;
    int tid = threadIdx.x;
#pragma unroll
    for (int p = 0; p < 8; p++) {
        int idx = tid + p * 256;
        int r = idx >> 6, c4 = (idx & 63) << 2;
        float4 v = *(const float4*)(W + (size_t)(k0 + r) * Nc + n0 + c4);
        Ws[r][c4] = v.x; Ws[r][c4 + 1] = v.y;
        Ws[r][c4 + 2] = v.z; Ws[r][c4 + 3] = v.w;
    }
    __syncthreads();
    float* out = pd.dst + ((size_t)(k0 >> 5) * (Nc >> 3) + (n0 >> 3)) * 256;
#pragma unroll
    for (int p = 0; p < 8; p++) {
        int q = tid + p * 256;
        int ntg = q >> 6;
        int r = q & 63;
        int kkd = r >> 4;
        int f0 = (r & 15) << 2;
        int L0 = f0 >> 1;
        int t0 = L0 & 3, g = L0 >> 2;
        int c = ntg * 8 + g;
        float4 o;
        o.x = tf32r(Ws[kkd * 8 + t0    ][c]);
        o.y = tf32r(Ws[kkd * 8 + t0 + 4][c]);
        o.z = tf32r(Ws[kkd * 8 + t0 + 1][c]);
        o.w = tf32r(Ws[kkd * 8 + t0 + 5][c]);
        *(float4*)(out + (size_t)q * 4) = o;
    }
}

// ---------------- LayerNorm (ROUND: tf32-round output for GEMM A) ----------
template<int ROUND>
__global__ void __launch_bounds__(256) ln_k(const float* __restrict__ X,
                                            const float* __restrict__ g,
                                            float* __restrict__ Y)
{
    int row = blockIdx.x;
    const float* x = X + (size_t)row * DIMd;
    int tid = threadIdx.x;
    float v[3]; float s = 0.f, sq = 0.f;
#pragma unroll
    for (int i = 0; i < 3; i++) {
        v[i] = x[tid + i * 256];
        s += v[i]; sq += v[i] * v[i];
    }
#pragma unroll
    for (int o = 16; o; o >>= 1) {
        s  += __shfl_xor_sync(~0u, s, o);
        sq += __shfl_xor_sync(~0u, sq, o);
    }
    __shared__ float red[2][8];
    int w = tid >> 5, lane = tid & 31;
    if (lane == 0) { red[0][w] = s; red[1][w] = sq; }
    __syncthreads();
    s = 0.f; sq = 0.f;
#pragma unroll
    for (int j = 0; j < 8; j++) { s += red[0][j]; sq += red[1][j]; }
    float mean = s * (1.f / DIMd);
    float var  = sq * (1.f / DIMd) - mean * mean;
    float rstd = rsqrtf(var + 1e-5f);
    float* y = Y + (size_t)row * DIMd;
#pragma unroll
    for (int i = 0; i < 3; i++) {
        int c = tid + i * 256;
        float o = (v[i] - mean) * rstd * g[c];
        y[c] = ROUND ? tf32r(o) : o;
    }
}

// ---------------- TF32 TC GEMM, tile 128x128, 2 CTAs/SM --------------------
// 8 warps: 4 (m) x 2 (n), each 32x64. A pre-rounded row-major, B packed.
// EPI: 0 none, 1 +bias, 2 gelu(x+b), 3 +res, 4 +bias+res
#define AS_LD 36
#define AS_SZ (128*AS_LD)     // 4608 floats
#define BS_SZ (16*256)        // 4096 floats (128 cols)
#define STG_SZ (AS_SZ + BS_SZ)
#define GEMM_SMEM (3*STG_SZ*4)   // 104448 B

template<int EPI>
__global__ void __launch_bounds__(256, 2) gemm_tc(const float* __restrict__ A,
                                                  const float* __restrict__ Wpk,
                                                  const float* __restrict__ bias,
                                                  const float* __restrict__ res,
                                                  float* __restrict__ C,
                                                  int K, int Nc)
{
    extern __shared__ float sm[];
    int tid = threadIdx.x;
    int warp = tid >> 5, lane = tid & 31;
    int g = lane >> 2, t = lane & 3;
    int wm = (warp >> 1) * 32;       // 0,32,64,96
    int warpn = warp & 1;            // 0,1
    int m0 = blockIdx.y * 128, n0 = blockIdx.x * 128;

    const float* Ag = A + (size_t)m0 * K;
    const float* Wg = Wpk + (size_t)(n0 >> 3) * 256;
    size_t wstride = (size_t)(Nc >> 3) * 256;   // per k-block

    float acc[2][8][4];
#pragma unroll
    for (int a = 0; a < 2; a++)
#pragma unroll
        for (int b = 0; b < 8; b++)
#pragma unroll
            for (int c = 0; c < 4; c++) acc[a][b][c] = 0.f;

    auto loadA = [&](int buf, int k0) {
        float* dst = sm + buf * STG_SZ;
#pragma unroll
        for (int p = 0; p < 4; p++) {
            int idx = tid + p * 256;
            int r = idx >> 3, c = (idx & 7) << 2;
            CPA16(cvta_s(dst + r * AS_LD + c), Ag + (size_t)r * K + k0 + c);
        }
    };
    auto loadW = [&](int buf, int kb) {
        float* dst = sm + buf * STG_SZ + AS_SZ;
        const float* src = Wg + (size_t)kb * wstride;
#pragma unroll
        for (int p = 0; p < 4; p++) {
            int gi = tid + p * 256;
            CPA16(cvta_s(dst + gi * 4), src + (size_t)gi * 4);
        }
    };

    int niter = K / 32;
    loadA(0, 0); loadW(0, 0); CPCOMMIT();
    loadA(1, 32); loadW(1, 1); CPCOMMIT();

    for (int it = 0; it < niter; it++) {
        if (it + 1 < niter) { CPWAIT1(); } else { CPWAIT0(); }
        __syncthreads();
        if (it + 2 < niter) {
            loadA((it + 2) % 3, (it + 2) * 32);
            loadW((it + 2) % 3, it + 2);
            CPCOMMIT();
        }
        const float* As = sm + (it % 3) * STG_SZ;
        const float* Bs = As + AS_SZ;

#pragma unroll
        for (int kkd = 0; kkd < 4; kkd++) {
            float af[2][4], bf[8][2];
#pragma unroll
            for (int mt = 0; mt < 2; mt++) {
                int r = wm + mt * 16 + g;
                af[mt][0] = As[r * AS_LD + kkd * 8 + t];
                af[mt][1] = As[(r + 8) * AS_LD + kkd * 8 + t];
                af[mt][2] = As[r * AS_LD + kkd * 8 + t + 4];
                af[mt][3] = As[(r + 8) * AS_LD + kkd * 8 + t + 4];
            }
#pragma unroll
            for (int nt = 0; nt < 8; nt++) {
                float2 bb = *(const float2*)&Bs[((warpn * 8 + nt) * 4 + kkd) * 64 + lane * 2];
                bf[nt][0] = bb.x; bf[nt][1] = bb.y;
            }
#pragma unroll
            for (int mt = 0; mt < 2; mt++)
#pragma unroll
                for (int nt = 0; nt < 8; nt++)
                    mma8(acc[mt][nt][0], acc[mt][nt][1],
                         acc[mt][nt][2], acc[mt][nt][3],
                         af[mt][0], af[mt][1], af[mt][2], af[mt][3],
                         bf[nt][0], bf[nt][1]);
        }
        __syncthreads();
    }

    int wn = warpn * 64;
#pragma unroll
    for (int mt = 0; mt < 2; mt++) {
        int row = m0 + wm + mt * 16 + g;
#pragma unroll
        for (int nt = 0; nt < 8; nt++) {
            int col = n0 + wn + nt * 8 + 2 * t;
            float v0 = acc[mt][nt][0], v1 = acc[mt][nt][1];
            float v2 = acc[mt][nt][2], v3 = acc[mt][nt][3];
            if (EPI == 1 || EPI == 2 || EPI == 4) {
                float b0 = bias[col], b1 = bias[col + 1];
                v0 += b0; v1 += b1; v2 += b0; v3 += b1;
            }
            if (EPI == 2) {
                v0 = tf32r(0.5f * v0 * (1.0f + erff(v0 * 0.70710678118654752f)));
                v1 = tf32r(0.5f * v1 * (1.0f + erff(v1 * 0.70710678118654752f)));
                v2 = tf32r(0.5f * v2 * (1.0f + erff(v2 * 0.70710678118654752f)));
                v3 = tf32r(0.5f * v3 * (1.0f + erff(v3 * 0.70710678118654752f)));
            }
            size_t o0 = (size_t)row * Nc + col;
            size_t o1 = (size_t)(row + 8) * Nc + col;
            if (EPI == 3 || EPI == 4) {
                float2 r0 = *(const float2*)(res + o0);
                float2 r1 = *(const float2*)(res + o1);
                v0 += r0.x; v1 += r0.y; v2 += r1.x; v3 += r1.y;
            }
            *(float2*)(C + o0) = make_float2(v0, v1);
            *(float2*)(C + o1) = make_float2(v2, v3);
        }
    }
}

// -------- QK RMSNorm + 2D RoPE + tf32 round (also rounds V) ---------------
__global__ void __launch_bounds__(256) qkrope_k(float* __restrict__ Q,
                                                float* __restrict__ KV,
                                                const float* __restrict__ qg,
                                                const float* __restrict__ kg,
                                                const int* __restrict__ h_idx,
                                                const int* __restrict__ w_idx)
{
    int warp = blockIdx.x * 8 + (threadIdx.x >> 5);
    int lane = threadIdx.x & 31;
    int grp = warp / (Mrows * Hh);       // 0=Q, 1=K, 2=V
    int rid = warp - grp * (Mrows * Hh);
    int bn = rid / Hh;
    int h  = rid % Hh;

    if (grp == 2) {  // V: round only
        float* ptr = KV + (size_t)bn * 2 * DIMd + DIMd + h * DHd;
        ptr[lane]      = tf32r(ptr[lane]);
        ptr[lane + 32] = tf32r(ptr[lane + 32]);
        return;
    }

    float* ptr;
    const float* g;
    if (grp == 0) { ptr = Q  + (size_t)bn * DIMd     + h * DHd; g = qg + h * DHd; }
    else          { ptr = KV + (size_t)bn * 2 * DIMd + h * DHd; g = kg + h * DHd; }

    float v1 = ptr[lane], v2 = ptr[lane + 32];
    float ss = v1 * v1 + v2 * v2;
#pragma unroll
    for (int o = 16; o; o >>= 1) ss += __shfl_xor_sync(~0u, ss, o);
    float sc = 8.0f / fmaxf(sqrtf(ss), 1e-12f);
    v1 = v1 * sc * g[lane];
    v2 = v2 * sc * g[lane + 32];

    int f = lane & 15;
    float invf = exp2f(-(float)f * (13.287712379549449f / 16.0f));
    float th1 = (float)h_idx[bn] * invf;
    float th2 = (float)w_idx[bn] * invf;
    float p1 = __shfl_xor_sync(~0u, v1, 16);
    float p2 = __shfl_xor_sync(~0u, v2, 16);
    float rh1 = (lane < 16) ? -p1 : p1;
    float rh2 = (lane < 16) ? -p2 : p2;
    ptr[lane]      = tf32r(v1 * cosf(th1) + rh1 * sinf(th1));
    ptr[lane + 32] = tf32r(v2 * cosf(th2) + rh2 * sinf(th2));
}

// ---------------- TF32 TC flash attention ----------------------------------
// 256 threads = 8 warps x 16 q-rows. Q in registers, cp.async K/V double buf.
#define KS_LD 68
#define VS_LD 72
#define PS_LD 68
#define ATT_SMEM ((2*64*KS_LD + 2*64*VS_LD + 128*PS_LD) * 4)   // 106496

__global__ void __launch_bounds__(256) attn_tc(const float* __restrict__ Q,
                                               const float* __restrict__ KV,
                                               const int* __restrict__ lengths,
                                               float* __restrict__ O)
{
    extern __shared__ float sm[];
    float* KsB = sm;                       // 2 x [64][KS_LD]
    float* VsB = KsB + 2 * 64 * KS_LD;     // 2 x [64][VS_LD]
    float* Ps  = VsB + 2 * 64 * VS_LD;     // [128][PS_LD]

    int b = blockIdx.z, h = blockIdx.y, q0 = blockIdx.x * 128;
    int tid = threadIdx.x;
    int warp = tid >> 5, lane = tid & 31;
    int g = lane >> 2, t = lane & 3;
    int wq = warp * 16;

    const float* Qg = Q  + ((size_t)b * Nn + q0) * DIMd + h * DHd;
    const float* Kg = KV + ((size_t)b * Nn) * 2 * DIMd + h * DHd;
    int len = lengths[b];

    // Q fragments in registers (pre-rounded by qkrope)
    float qf[8][4];
    {
        const float* r0 = Qg + (size_t)(wq + g) * DIMd;
        const float* r1 = r0 + 8 * DIMd;
#pragma unroll
        for (int kk = 0; kk < 8; kk++) {
            qf[kk][0] = r0[kk * 8 + t];
            qf[kk][1] = r1[kk * 8 + t];
            qf[kk][2] = r0[kk * 8 + t + 4];
            qf[kk][3] = r1[kk * 8 + t + 4];
        }
    }

    float Oa[8][4];
    float mrow[2], lrow[2];
#pragma unroll
    for (int n = 0; n < 8; n++)
#pragma unroll
        for (int c = 0; c < 4; c++) Oa[n][c] = 0.f;
    mrow[0] = mrow[1] = -1e30f;
    lrow[0] = lrow[1] = 0.f;

    int ntiles = (len + 63) >> 6;

    auto loadKV = [&](int buf, int kt) {
        float* Kd = KsB + buf * 64 * KS_LD;
        float* Vd = VsB + buf * 64 * VS_LD;
#pragma unroll
        for (int p = 0; p < 4; p++) {
            int idx = tid + p * 256;      // 1024 float4 per tile
            int r = idx >> 4, c = (idx & 15) << 2;
            const float* kp = Kg + (size_t)(kt * 64 + r) * (2 * DIMd) + c;
            CPA16(cvta_s(Kd + r * KS_LD + c), kp);
            CPA16(cvta_s(Vd + r * VS_LD + c), kp + DIMd);
        }
    };

    loadKV(0, 0); CPCOMMIT();

    for (int kt = 0; kt < ntiles; kt++) {
        CPWAIT0();
        __syncthreads();
        if (kt + 1 < ntiles) { loadKV((kt + 1) & 1, kt + 1); CPCOMMIT(); }
        const float* Ks = KsB + (kt & 1) * 64 * KS_LD;
        const float* Vs = VsB + (kt & 1) * 64 * VS_LD;

        // S = Q K^T
        float S[8][4];
#pragma unroll
        for (int n = 0; n < 8; n++)
#pragma unroll
            for (int c = 0; c < 4; c++) S[n][c] = 0.f;

#pragma unroll
        for (int kk = 0; kk < 8; kk++) {
            float bf[8][2];
#pragma unroll
            for (int nt = 0; nt < 8; nt++) {
                int key = nt * 8 + g;
                bf[nt][0] = Ks[key * KS_LD + kk * 8 + t];
                bf[nt][1] = Ks[key * KS_LD + kk * 8 + t + 4];
            }
#pragma unroll
            for (int nt = 0; nt < 8; nt++)
                mma8(S[nt][0], S[nt][1], S[nt][2], S[nt][3],
                     qf[kk][0], qf[kk][1], qf[kk][2], qf[kk][3],
                     bf[nt][0], bf[nt][1]);
        }

        // key mask
#pragma unroll
        for (int nt = 0; nt < 8; nt++) {
            int kc = kt * 64 + nt * 8 + 2 * t;
            if (kc >= len)     { S[nt][0] = -1e30f; S[nt][2] = -1e30f; }
            if (kc + 1 >= len) { S[nt][1] = -1e30f; S[nt][3] = -1e30f; }
        }

        // online softmax: half 0 -> rows g (slots 0,1); half 1 -> rows g+8 (2,3)
#pragma unroll
        for (int half = 0; half < 2; half++) {
            int i0 = half * 2, i1 = half * 2 + 1;
            float rm = -1e30f;
#pragma unroll
            for (int nt = 0; nt < 8; nt++)
                rm = fmaxf(rm, fmaxf(S[nt][i0], S[nt][i1]));
            rm = fmaxf(rm, __shfl_xor_sync(~0u, rm, 1));
            rm = fmaxf(rm, __shfl_xor_sync(~0u, rm, 2));
            float mn = fmaxf(mrow[half], rm);
            float rs = 0.f;
#pragma unroll
            for (int nt = 0; nt < 8; nt++) {
                S[nt][i0] = __expf(S[nt][i0] - mn);
                S[nt][i1] = __expf(S[nt][i1] - mn);
                rs += S[nt][i0] + S[nt][i1];
            }
            rs += __shfl_xor_sync(~0u, rs, 1);
            rs += __shfl_xor_sync(~0u, rs, 2);
            float corr = __expf(mrow[half] - mn);
            lrow[half] = lrow[half] * corr + rs;
            mrow[half] = mn;
#pragma unroll
            for (int nt = 0; nt < 8; nt++) {
                Oa[nt][i0] *= corr;
                Oa[nt][i1] *= corr;
            }
        }

        // stage P (per-warp-private rows -> __syncwarp suffices)
        {
            int r = wq + g;
#pragma unroll
            for (int nt = 0; nt < 8; nt++) {
                int c = nt * 8 + 2 * t;
                *(float2*)&Ps[r * PS_LD + c] =
                    make_float2(tf32r(S[nt][0]), tf32r(S[nt][1]));
                *(float2*)&Ps[(r + 8) * PS_LD + c] =
                    make_float2(tf32r(S[nt][2]), tf32r(S[nt][3]));
            }
        }
        __syncwarp();

        // O += P V
#pragma unroll
        for (int kk = 0; kk < 8; kk++) {
            float af[4], bf[8][2];
            af[0] = Ps[(wq + g) * PS_LD + kk * 8 + t];
            af[1] = Ps[(wq + 8 + g) * PS_LD + kk * 8 + t];
            af[2] = Ps[(wq + g) * PS_LD + kk * 8 + t + 4];
            af[3] = Ps[(wq + 8 + g) * PS_LD + kk * 8 + t + 4];
#pragma unroll
            for (int nt = 0; nt < 8; nt++) {
                int c = nt * 8 + g;
                bf[nt][0] = Vs[(kk * 8 + t) * VS_LD + c];
                bf[nt][1] = Vs[(kk * 8 + t + 4) * VS_LD + c];
            }
#pragma unroll
            for (int nt = 0; nt < 8; nt++)
                mma8(Oa[nt][0], Oa[nt][1], Oa[nt][2], Oa[nt][3],
                     af[0], af[1], af[2], af[3],
                     bf[nt][0], bf[nt][1]);
        }
    }

    // write out rounded (ao is only ever a GEMM A operand)
    {
        int row0 = q0 + wq + g;
        float inv0 = 1.0f / lrow[0];
        float inv1 = 1.0f / lrow[1];
#pragma unroll
        for (int nt = 0; nt < 8; nt++) {
            int col = h * DHd + nt * 8 + 2 * t;
            size_t o0 = ((size_t)b * Nn + row0) * DIMd + col;
            size_t o1 = ((size_t)b * Nn + row0 + 8) * DIMd + col;
            *(float2*)&O[o0] = make_float2(tf32r(Oa[nt][0] * inv0),
                                           tf32r(Oa[nt][1] * inv0));
            *(float2*)&O[o1] = make_float2(tf32r(Oa[nt][2] * inv1),
                                           tf32r(Oa[nt][3] * inv1));
        }
    }
}

// ---------------- mask tail writer -----------------------------------------
__global__ void mask_k(const int* __restrict__ lengths, float* __restrict__ out)
{
    int i = blockIdx.x * blockDim.x + threadIdx.x;
    if (i < Bb * Nn) {
        int b = i / Nn, n = i % Nn;
        out[i] = (n < lengths[b]) ? 1.0f : 0.0f;
    }
}

// ---------------- host orchestration ---------------------------------------
extern "C" void kernel_launch(void* const* d_in, const int* in_sizes, int n_in,
                              void* d_out, int out_size)
{
    const float* patches    = (const float*)d_in[0];
    const float* pe_ln1_g   = (const float*)d_in[1];
    const float* pe_W       = (const float*)d_in[2];
    const float* pe_b       = (const float*)d_in[3];
    const float* pe_ln2_g   = (const float*)d_in[4];
    const float* attn_ln_g  = (const float*)d_in[5];
    const float* qn_g       = (const float*)d_in[6];
    const float* kn_g       = (const float*)d_in[7];
    const float* Wq         = (const float*)d_in[8];
    const float* Wkv        = (const float*)d_in[9];
    const float* Wo         = (const float*)d_in[10];
    const float* ff_ln_g    = (const float*)d_in[11];
    const float* W1         = (const float*)d_in[12];
    const float* b1         = (const float*)d_in[13];
    const float* W2         = (const float*)d_in[14];
    const float* b2         = (const float*)d_in[15];
    const float* final_ln_g = (const float*)d_in[16];
    const int*   h_idx      = (const int*)d_in[17];
    const int*   w_idx      = (const int*)d_in[18];
    const int*   lengths    = (const int*)d_in[19];

    float *x, *xn, *q, *kv, *ao, *hb, *wpk;
    cudaGetSymbolAddress((void**)&x,   g_x);
    cudaGetSymbolAddress((void**)&xn,  g_xn);
    cudaGetSymbolAddress((void**)&q,   g_q);
    cudaGetSymbolAddress((void**)&kv,  g_kv);
    cudaGetSymbolAddress((void**)&ao,  g_ao);
    cudaGetSymbolAddress((void**)&hb,  g_h);
    cudaGetSymbolAddress((void**)&wpk, g_wpk);

    cudaFuncSetAttribute(gemm_tc<0>, cudaFuncAttributeMaxDynamicSharedMemorySize, GEMM_SMEM);
    cudaFuncSetAttribute(gemm_tc<1>, cudaFuncAttributeMaxDynamicSharedMemorySize, GEMM_SMEM);
    cudaFuncSetAttribute(gemm_tc<2>, cudaFuncAttributeMaxDynamicSharedMemorySize, GEMM_SMEM);
    cudaFuncSetAttribute(gemm_tc<3>, cudaFuncAttributeMaxDynamicSharedMemorySize, GEMM_SMEM);
    cudaFuncSetAttribute(gemm_tc<4>, cudaFuncAttributeMaxDynamicSharedMemorySize, GEMM_SMEM);
    cudaFuncSetAttribute(attn_tc, cudaFuncAttributeMaxDynamicSharedMemorySize, ATT_SMEM);

    dim3 t256(256);

    // ---- weight offsets inside g_wpk (floats) ------------------------------
    size_t off_pe = 0;
    size_t off_q [Ll], off_kv[Ll], off_o[Ll], off_1[Ll], off_2[Ll];
    {
        size_t cur = (size_t)DIMd * DIMd;
        for (int i = 0; i < Ll; i++) {
            off_q [i] = cur; cur += (size_t)DIMd * DIMd;
            off_kv[i] = cur; cur += (size_t)DIMd * 2 * DIMd;
            off_o [i] = cur; cur += (size_t)DIMd * DIMd;
            off_1 [i] = cur; cur += (size_t)DIMd * MLPm;
            off_2 [i] = cur; cur += (size_t)MLPm * DIMd;
        }
    }

    // ---- single-launch pack of all 11 weight matrices ----------------------
    PackTable tab;
    int ti = 0;
    tab.d[ti++] = { pe_W, wpk + off_pe, DIMd, DIMd };
    for (int i = 0; i < Ll; i++) {
        tab.d[ti++] = { Wq  + (size_t)i * DIMd * DIMd,     wpk + off_q [i], DIMd, DIMd };
        tab.d[ti++] = { Wkv + (size_t)i * DIMd * 2 * DIMd, wpk + off_kv[i], DIMd, 2 * DIMd };
        tab.d[ti++] = { Wo  + (size_t)i * DIMd * DIMd,     wpk + off_o [i], DIMd, DIMd };
        tab.d[ti++] = { W1  + (size_t)i * DIMd * MLPm,     wpk + off_1 [i], DIMd, MLPm };
        tab.d[ti++] = { W2  + (size_t)i * MLPm * DIMd,     wpk + off_2 [i], MLPm, DIMd };
    }
    pack_all<<<dim3(288, 11), t256>>>(tab);   // max tiles = W1/W2 = 288

    dim3 gN768(DIMd / 128, Mrows / 128);       // (6, 64)
    dim3 gN1536(2 * DIMd / 128, Mrows / 128);  // (12, 64)
    dim3 gN3072(MLPm / 128, Mrows / 128);      // (24, 64)

    // patch embedding: LN -> Linear+bias -> LN
    ln_k<1><<<Mrows, t256>>>(patches, pe_ln1_g, xn);
    gemm_tc<1><<<gN768, t256, GEMM_SMEM>>>(xn, wpk + off_pe, pe_b, nullptr, x, DIMd, DIMd);
    ln_k<0><<<Mrows, t256>>>(x, pe_ln2_g, x);

    for (int i = 0; i < Ll; i++) {
        ln_k<1><<<Mrows, t256>>>(x, attn_ln_g + (size_t)i * DIMd, xn);
        gemm_tc<0><<<gN768, t256, GEMM_SMEM>>>(xn, wpk + off_q[i], nullptr, nullptr, q, DIMd, DIMd);
        gemm_tc<0><<<gN1536, t256, GEMM_SMEM>>>(xn, wpk + off_kv[i], nullptr, nullptr, kv, DIMd, 2 * DIMd);
        qkrope_k<<<(3 * Mrows * Hh) / 8, t256>>>(
            q, kv, qn_g + (size_t)i * Hh * DHd, kn_g + (size_t)i * Hh * DHd,
            h_idx, w_idx);
        attn_tc<<<dim3(Nn / 128, Hh, Bb), t256, ATT_SMEM>>>(q, kv, lengths, ao);
        gemm_tc<3><<<gN768, t256, GEMM_SMEM>>>(ao, wpk + off_o[i], nullptr, x, x, DIMd, DIMd);
        ln_k<1><<<Mrows, t256>>>(x, ff_ln_g + (size_t)i * DIMd, xn);
        gemm_tc<2><<<gN3072, t256, GEMM_SMEM>>>(xn, wpk + off_1[i], b1 + (size_t)i * MLPm, nullptr, hb, DIMd, MLPm);
        gemm_tc<4><<<gN768, t256, GEMM_SMEM>>>(hb, wpk + off_2[i], b2 + (size_t)i * DIMd, x, x, MLPm, DIMd);
    }

    ln_k<0><<<Mrows, t256>>>(x, final_ln_g, (float*)d_out);

    if (out_size > Mrows * DIMd) {
        mask_k<<<(Bb * Nn + 255) / 256, t256>>>(lengths,
                                                (float*)d_out + (size_t)Mrows * DIMd);
    }
}